// round 8
// baseline (speedup 1.0000x reference)
#include <cuda_runtime.h>
#include <cuda_bf16.h>

typedef unsigned int u32;

#define B_   8
#define N_   1024
#define C_   1024
#define H_   16
#define D_   64
#define M_   (B_ * N_)     // 8192
#define QKVC 3072
#define BH_  (B_ * H_)     // 128

// ---------------- allocation-free scratch (device globals) ----------------
__device__ __align__(256) __nv_bfloat16 g_xh[(size_t)M_ * C_],  g_xl[(size_t)M_ * C_];
__device__ __align__(256) __nv_bfloat16 g_wqh[(size_t)QKVC * C_], g_wql[(size_t)QKVC * C_];
__device__ __align__(256) __nv_bfloat16 g_qh[(size_t)BH_ * N_ * D_], g_ql[(size_t)BH_ * N_ * D_];
__device__ __align__(256) __nv_bfloat16 g_kh[(size_t)BH_ * N_ * D_], g_kl[(size_t)BH_ * N_ * D_];
__device__ __align__(256) __nv_bfloat16 g_vTh[(size_t)BH_ * D_ * N_], g_vTl[(size_t)BH_ * D_ * N_];
// int8 path: ctx digits + per-tile scales, w_proj^T digits
__device__ __align__(256) signed char g_c1[(size_t)M_ * C_], g_c2[(size_t)M_ * C_];
__device__ __align__(256) signed char g_w1[(size_t)C_ * C_], g_w2[(size_t)C_ * C_];
__device__ __align__(256) float g_cscale[(M_ / 128) * 16];

// ---------------- helpers ----------------
__device__ __forceinline__ u32 smem_u32(const void* p) {
    u32 a;
    asm("{ .reg .u64 t; cvta.to.shared.u64 t, %1; cvt.u32.u64 %0, t; }" : "=r"(a) : "l"(p));
    return a;
}
#define CP16(dst, src) \
    asm volatile("cp.async.cg.shared.global [%0], [%1], 16;" :: "r"(dst), "l"(src) : "memory")
#define CP_COMMIT() asm volatile("cp.async.commit_group;" ::: "memory")
#define CP_WAIT(n)  asm volatile("cp.async.wait_group %0;" :: "n"(n) : "memory")

__device__ __forceinline__ void ldm4(u32& r0, u32& r1, u32& r2, u32& r3, u32 a) {
    asm volatile("ldmatrix.sync.aligned.m8n8.x4.shared.b16 {%0,%1,%2,%3}, [%4];"
        : "=r"(r0), "=r"(r1), "=r"(r2), "=r"(r3) : "r"(a));
}
__device__ __forceinline__ void mma16816(float* c, const u32* a, const u32* b) {
    asm volatile(
        "mma.sync.aligned.m16n8k16.row.col.f32.bf16.bf16.f32 "
        "{%0,%1,%2,%3}, {%4,%5,%6,%7}, {%8,%9}, {%0,%1,%2,%3};"
        : "+f"(c[0]), "+f"(c[1]), "+f"(c[2]), "+f"(c[3])
        : "r"(a[0]), "r"(a[1]), "r"(a[2]), "r"(a[3]), "r"(b[0]), "r"(b[1]));
}
__device__ __forceinline__ void imma16832(int* c, const u32* a, const u32* b) {
    asm volatile(
        "mma.sync.aligned.m16n8k32.row.col.s32.s8.s8.s32 "
        "{%0,%1,%2,%3}, {%4,%5,%6,%7}, {%8,%9}, {%0,%1,%2,%3};"
        : "+r"(c[0]), "+r"(c[1]), "+r"(c[2]), "+r"(c[3])
        : "r"(a[0]), "r"(a[1]), "r"(a[2]), "r"(a[3]), "r"(b[0]), "r"(b[1]));
}
__device__ __forceinline__ void splitf(float v, __nv_bfloat16& h, __nv_bfloat16& l) {
    h = __float2bfloat16(v);
    l = __float2bfloat16(v - __bfloat162float(h));
}
// 2-digit s8 quantization: v ~= (d1*128 + d2) * (R/16256), inv = 16256/R
__device__ __forceinline__ void quant2(float v, float inv, signed char& d1, signed char& d2) {
    float q = fminf(fmaxf(v * inv, -16256.f), 16256.f);
    int vi = __float2int_rn(q);
    int t1 = (vi + 64) >> 7;
    d1 = (signed char)t1;
    d2 = (signed char)(vi - (t1 << 7));
}

// ---------------------------------------------------------------------------
// Split-bf16 HMMA GEMM for QKV (unchanged control: 256 thr, MA4 NA4, 3-stage)
// ---------------------------------------------------------------------------
__global__ void __launch_bounds__(256, 1) qkv_gemm()
{
    constexpr int NC    = 32;
    constexpr int MA    = 4;
    constexpr int NA    = 4;
    constexpr int APART = 128 * 80;
    constexpr int BPART = 128 * 80;
    constexpr int STAGE = 2 * APART + 2 * BPART;

    extern __shared__ char smem[];
    const u32 sb   = smem_u32(smem);
    const int tid  = threadIdx.x;
    const int wid  = tid >> 5, lane = tid & 31;
    const int g    = lane >> 2, t = lane & 3;
    const int bn   = blockIdx.x * 128;
    const int bm   = blockIdx.y * 128;
    const int wm   = (wid & 1) * 64;
    const int wn   = (wid >> 1) * 32;

    const __nv_bfloat16 *Ah = g_xh + (size_t)bm * C_, *Al = g_xl + (size_t)bm * C_;
    const __nv_bfloat16 *Bh = g_wqh + (size_t)bn * C_, *Bl = g_wql + (size_t)bn * C_;

    float acc[MA][NA][4];
    #pragma unroll
    for (int i = 0; i < MA; i++)
        #pragma unroll
        for (int j = 0; j < NA; j++)
            #pragma unroll
            for (int r = 0; r < 4; r++) acc[i][j][r] = 0.0f;

    auto issue_loads = [&](int ck, int s) {
        const int kofs = ck * 32;
        const u32 base = sb + s * STAGE;
        #pragma unroll
        for (int i = tid; i < 128 * 4; i += 256) {
            int r = i >> 2, sgm = i & 3;
            u32 off = (u32)(r * 80 + sgm * 16);
            CP16(base + off,         Ah + (size_t)r * C_ + kofs + sgm * 8);
            CP16(base + APART + off, Al + (size_t)r * C_ + kofs + sgm * 8);
        }
        #pragma unroll
        for (int i = tid; i < 128 * 4; i += 256) {
            int r = i >> 2, sgm = i & 3;
            u32 off = (u32)(r * 80 + sgm * 16);
            CP16(base + 2 * APART + off,         Bh + (size_t)r * C_ + kofs + sgm * 8);
            CP16(base + 2 * APART + BPART + off, Bl + (size_t)r * C_ + kofs + sgm * 8);
        }
        CP_COMMIT();
    };

    const u32 arow = (u32)((wm + (lane & 15)) * 80 + ((lane >> 4) << 4));
    const u32 brow = (u32)((wn + (lane & 7) + ((lane >> 4) << 3)) * 80 + (((lane >> 3) & 1) << 4));

    auto do_compute = [&](int s) {
        const u32 abase = sb + s * STAGE;
        const u32 bbase = abase + 2 * APART;
        #pragma unroll
        for (int ks = 0; ks < 2; ks++) {
            const u32 kb = ks * 32;
            u32 a_hi[MA][4], a_lo[MA][4], b_hi[NA][2], b_lo[NA][2];
            #pragma unroll
            for (int ma = 0; ma < MA; ma++) {
                u32 ad = abase + arow + ma * 16 * 80 + kb;
                ldm4(a_hi[ma][0], a_hi[ma][1], a_hi[ma][2], a_hi[ma][3], ad);
                ldm4(a_lo[ma][0], a_lo[ma][1], a_lo[ma][2], a_lo[ma][3], ad + APART);
            }
            #pragma unroll
            for (int p = 0; p < NA / 2; p++) {
                u32 bd = bbase + brow + p * 16 * 80 + kb;
                ldm4(b_hi[2*p][0], b_hi[2*p][1], b_hi[2*p+1][0], b_hi[2*p+1][1], bd);
                ldm4(b_lo[2*p][0], b_lo[2*p][1], b_lo[2*p+1][0], b_lo[2*p+1][1], bd + BPART);
            }
            #pragma unroll
            for (int ma = 0; ma < MA; ma++)
                #pragma unroll
                for (int na = 0; na < NA; na++) {
                    mma16816(acc[ma][na], a_hi[ma], b_hi[na]);
                    mma16816(acc[ma][na], a_hi[ma], b_lo[na]);
                    mma16816(acc[ma][na], a_lo[ma], b_hi[na]);
                }
        }
    };

    issue_loads(0, 0);
    issue_loads(1, 1);
    for (int ck = 0; ck < NC; ck++) {
        const int s = ck % 3;
        if (ck + 2 < NC) { issue_loads(ck + 2, (ck + 2) % 3); CP_WAIT(2); }
        else if (ck + 1 < NC) { CP_WAIT(1); }
        else { CP_WAIT(0); }
        __syncthreads();
        do_compute(s);
        __syncthreads();
    }

    // ---- epilogue: scatter q(scaled)/k/vT hi+lo ----
    #pragma unroll
    for (int ma = 0; ma < MA; ma++)
        #pragma unroll
        for (int na = 0; na < NA; na++)
            #pragma unroll
            for (int half = 0; half < 2; half++) {
                const int row = bm + wm + ma * 16 + g + half * 8;
                const int col = bn + wn + na * 8 + t * 2;
                float v0 = acc[ma][na][half * 2 + 0];
                float v1 = acc[ma][na][half * 2 + 1];

                const int which = col >> 10;
                const int c     = col & 1023;
                const int h     = c >> 6;
                const int d0    = c & 63;
                const int b8    = row >> 10;
                const int n     = row & 1023;
                const int bh    = b8 * H_ + h;
                if (which == 0) {
                    __nv_bfloat16 h0, l0, h1, l1;
                    splitf(v0 * 0.125f, h0, l0); splitf(v1 * 0.125f, h1, l1);
                    const size_t base = ((size_t)bh * N_ + n) * D_ + d0;
                    *(__nv_bfloat162*)(g_qh + base) = __nv_bfloat162(h0, h1);
                    *(__nv_bfloat162*)(g_ql + base) = __nv_bfloat162(l0, l1);
                } else if (which == 1) {
                    __nv_bfloat16 h0, l0, h1, l1;
                    splitf(v0, h0, l0); splitf(v1, h1, l1);
                    const size_t base = ((size_t)bh * N_ + n) * D_ + d0;
                    *(__nv_bfloat162*)(g_kh + base) = __nv_bfloat162(h0, h1);
                    *(__nv_bfloat162*)(g_kl + base) = __nv_bfloat162(l0, l1);
                } else {
                    __nv_bfloat16 h0, l0, h1, l1;
                    splitf(v0, h0, l0); splitf(v1, h1, l1);
                    const size_t vb = (size_t)bh * D_ * N_ + n;
                    g_vTh[vb + (size_t)d0 * N_]       = h0;
                    g_vTh[vb + (size_t)(d0 + 1) * N_] = h1;
                    g_vTl[vb + (size_t)d0 * N_]       = l0;
                    g_vTl[vb + (size_t)(d0 + 1) * N_] = l1;
                }
            }
}

// ---------------------------------------------------------------------------
// Fused S = qk^T -> softmax -> attn fp32 out ONLY (unchanged from r7).
// ---------------------------------------------------------------------------
#define Q_OFF  0
#define QL_OFF 4608
#define K_OFF  9216
#define KSTG   36864
#define KL_OFF 18432
#define S_OFF  82944
#define S_PIT  4144
#define SS_SMEM (S_OFF + 32 * S_PIT)   // 215552

__global__ void __launch_bounds__(256, 1) sscore_kernel(float* __restrict__ attn)
{
    extern __shared__ char smem[];
    const u32 sb   = smem_u32(smem);
    const int tid  = threadIdx.x;
    const int wid  = tid >> 5, lane = tid & 31;
    const int g    = lane >> 2, t = lane & 3;

    const int bh   = blockIdx.x >> 5;
    const int row0 = (blockIdx.x & 31) * 32;
    const int wm   = (wid & 1) * 16;
    const int wn   = (wid >> 1) * 32;

    const __nv_bfloat16* Qh = g_qh + ((size_t)bh * N_ + row0) * D_;
    const __nv_bfloat16* Ql = g_ql + ((size_t)bh * N_ + row0) * D_;
    const __nv_bfloat16* Kh = g_kh + (size_t)bh * N_ * D_;
    const __nv_bfloat16* Kl = g_kl + (size_t)bh * N_ * D_;

    {
        int r = tid >> 3, sgm = tid & 7;
        u32 off = (u32)(r * 144 + sgm * 16);
        *(float4*)(smem + Q_OFF + off)  = *(const float4*)(Qh + r * D_ + sgm * 8);
        *(float4*)(smem + QL_OFF + off) = *(const float4*)(Ql + r * D_ + sgm * 8);
    }

    auto issueK = [&](int c, int s) {
        const u32 base = sb + K_OFF + s * KSTG;
        const size_t ko = (size_t)c * 128 * D_;
        #pragma unroll
        for (int i = tid; i < 128 * 8; i += 256) {
            int r = i >> 3, sgm = i & 7;
            u32 off = (u32)(r * 144 + sgm * 16);
            CP16(base + off,          Kh + ko + r * D_ + sgm * 8);
            CP16(base + KL_OFF + off, Kl + ko + r * D_ + sgm * 8);
        }
        CP_COMMIT();
    };

    const u32 arow = (u32)((wm + (lane & 15)) * 144 + ((lane >> 4) << 4));
    const u32 brow = (u32)((wn + (lane & 7) + ((lane >> 4) << 3)) * 144 + (((lane >> 3) & 1) << 4));

    issueK(0, 0);
    issueK(1, 1);
    for (int c = 0; c < 8; c++) {
        if (c < 7) CP_WAIT(1); else CP_WAIT(0);
        __syncthreads();

        const u32 kb0 = sb + K_OFF + (c & 1) * KSTG;
        float acc[4][4];
        #pragma unroll
        for (int j = 0; j < 4; j++)
            #pragma unroll
            for (int r = 0; r < 4; r++) acc[j][r] = 0.0f;

        #pragma unroll
        for (int ks = 0; ks < 4; ks++) {
            const u32 kb = ks * 32;
            u32 a_hi[4], a_lo[4], b_hi[4][2], b_lo[4][2];
            u32 ad = sb + Q_OFF + arow + kb;
            ldm4(a_hi[0], a_hi[1], a_hi[2], a_hi[3], ad);
            ldm4(a_lo[0], a_lo[1], a_lo[2], a_lo[3], ad + QL_OFF);
            #pragma unroll
            for (int p = 0; p < 2; p++) {
                u32 bd = kb0 + brow + p * 16 * 144 + kb;
                ldm4(b_hi[2*p][0], b_hi[2*p][1], b_hi[2*p+1][0], b_hi[2*p+1][1], bd);
                ldm4(b_lo[2*p][0], b_lo[2*p][1], b_lo[2*p+1][0], b_lo[2*p+1][1], bd + KL_OFF);
            }
            #pragma unroll
            for (int na = 0; na < 4; na++) {
                mma16816(acc[na], a_hi, b_hi[na]);
                mma16816(acc[na], a_hi, b_lo[na]);
                mma16816(acc[na], a_lo, b_hi[na]);
            }
        }

        #pragma unroll
        for (int na = 0; na < 4; na++)
            #pragma unroll
            for (int half = 0; half < 2; half++) {
                int row = wm + g + half * 8;
                int col = c * 128 + wn + na * 8 + t * 2;
                *(float2*)(smem + S_OFF + row * S_PIT + col * 4) =
                    make_float2(acc[na][half * 2], acc[na][half * 2 + 1]);
            }

        __syncthreads();
        if (c + 2 < 8) issueK(c + 2, c & 1);
    }

    #pragma unroll
    for (int rr = 0; rr < 4; rr++) {
        const int r = wid * 4 + rr;
        const float* Srow = (const float*)(smem + S_OFF + r * S_PIT);
        float4 f[8];
        float m = -1e30f;
        #pragma unroll
        for (int i = 0; i < 8; i++) {
            f[i] = *(const float4*)(Srow + (lane + i * 32) * 4);
            m = fmaxf(m, fmaxf(fmaxf(f[i].x, f[i].y), fmaxf(f[i].z, f[i].w)));
        }
        #pragma unroll
        for (int o = 16; o > 0; o >>= 1) m = fmaxf(m, __shfl_xor_sync(0xffffffffu, m, o));
        float s = 0.0f;
        #pragma unroll
        for (int i = 0; i < 8; i++) {
            f[i].x = __expf(f[i].x - m); f[i].y = __expf(f[i].y - m);
            f[i].z = __expf(f[i].z - m); f[i].w = __expf(f[i].w - m);
            s += f[i].x + f[i].y + f[i].z + f[i].w;
        }
        #pragma unroll
        for (int o = 16; o > 0; o >>= 1) s += __shfl_xor_sync(0xffffffffu, s, o);
        const float inv = 1.0f / s;

        float* ap = attn + ((size_t)bh * N_ + row0 + r) * N_;
        #pragma unroll
        for (int i = 0; i < 8; i++) {
            *(float4*)(ap + (lane + i * 32) * 4) =
                make_float4(f[i].x * inv, f[i].y * inv, f[i].z * inv, f[i].w * inv);
        }
    }
}

// ---------------------------------------------------------------------------
// AV GEMM (unchanged compute) — NEW epilogue: per-tile dynamic int8 digits.
// ---------------------------------------------------------------------------
#define AV_ASTG   18432
#define AV_AH_OFF (3 * AV_ASTG)
#define AV_APART  10240
#define AV_B_OFF  (AV_AH_OFF + 2 * AV_APART)
#define AV_BSTG   10240
#define AV_SMEM   (AV_B_OFF + 3 * AV_BSTG)         // 106496

__global__ void __launch_bounds__(256, 1) av_gemm(const float* __restrict__ attn)
{
    extern __shared__ char smem[];
    const u32 sb   = smem_u32(smem);
    const int tid  = threadIdx.x;
    const int wid  = tid >> 5, lane = tid & 31;
    const int g    = lane >> 2, t = lane & 3;

    const int bm = blockIdx.y * 128;
    const int z  = blockIdx.z;
    const int b8 = z >> 4, h = z & 15;
    const int wm = (wid & 3) * 32;
    const int wn = (wid >> 2) * 32;

    const float* Ap = attn + (size_t)z * N_ * N_ + (size_t)bm * N_;
    const __nv_bfloat16* Vh = g_vTh + (size_t)z * D_ * N_;
    const __nv_bfloat16* Vl = g_vTl + (size_t)z * D_ * N_;

    float acc[2][4][4];
    #pragma unroll
    for (int i = 0; i < 2; i++)
        #pragma unroll
        for (int j = 0; j < 4; j++)
            #pragma unroll
            for (int r = 0; r < 4; r++) acc[i][j][r] = 0.0f;

    auto issue_loads = [&](int ck, int s) {
        const int kofs = ck * 32;
        const u32 abase = sb + s * AV_ASTG;
        #pragma unroll
        for (int i = tid; i < 128 * 8; i += 256) {
            int r = i >> 3, sgm = i & 7;
            CP16(abase + (u32)(r * 144 + sgm * 16), Ap + (size_t)r * N_ + kofs + sgm * 4);
        }
        const u32 bbase = sb + AV_B_OFF + s * AV_BSTG;
        #pragma unroll
        for (int i = tid; i < 64 * 4; i += 256) {
            int r = i >> 2, sgm = i & 3;
            u32 off = (u32)(r * 80 + sgm * 16);
            CP16(bbase + off,        Vh + (size_t)r * N_ + kofs + sgm * 8);
            CP16(bbase + 5120 + off, Vl + (size_t)r * N_ + kofs + sgm * 8);
        }
        CP_COMMIT();
    };

    const u32 arow = (u32)((wm + (lane & 15)) * 80 + ((lane >> 4) << 4));
    const u32 brow = (u32)((wn + (lane & 7) + ((lane >> 4) << 3)) * 80 + (((lane >> 3) & 1) << 4));

    issue_loads(0, 0);
    issue_loads(1, 1);
    issue_loads(2, 2);
    for (int ck = 0; ck < 32; ck++) {
        const int s = ck % 3;
        if (ck <= 29) CP_WAIT(2);
        else if (ck == 30) CP_WAIT(1);
        else CP_WAIT(0);
        __syncthreads();

        {
            const char* src = smem + s * AV_ASTG + (tid >> 1) * 144 + (tid & 1) * 64;
            float4 v0 = *(const float4*)(src);
            float4 v1 = *(const float4*)(src + 16);
            float4 v2 = *(const float4*)(src + 32);
            float4 v3 = *(const float4*)(src + 48);
            float fv[16] = { v0.x,v0.y,v0.z,v0.w, v1.x,v1.y,v1.z,v1.w,
                             v2.x,v2.y,v2.z,v2.w, v3.x,v3.y,v3.z,v3.w };
            u32 hw[8], lw[8];
            #pragma unroll
            for (int p = 0; p < 8; p++) {
                __nv_bfloat16 h0, l0, h1, l1;
                splitf(fv[2*p],   h0, l0);
                splitf(fv[2*p+1], h1, l1);
                __nv_bfloat162 hh(h0, h1), ll(l0, l1);
                hw[p] = *(u32*)&hh; lw[p] = *(u32*)&ll;
            }
            char* dh = smem + AV_AH_OFF + (tid >> 1) * 80 + (tid & 1) * 32;
            char* dl = dh + AV_APART;
            *(uint4*)dh        = make_uint4(hw[0], hw[1], hw[2], hw[3]);
            *(uint4*)(dh + 16) = make_uint4(hw[4], hw[5], hw[6], hw[7]);
            *(uint4*)dl        = make_uint4(lw[0], lw[1], lw[2], lw[3]);
            *(uint4*)(dl + 16) = make_uint4(lw[4], lw[5], lw[6], lw[7]);
        }
        __syncthreads();

        {
            const u32 ah0 = sb + AV_AH_OFF;
            const u32 bb0 = sb + AV_B_OFF + s * AV_BSTG;
            #pragma unroll
            for (int ks = 0; ks < 2; ks++) {
                const u32 kb = ks * 32;
                u32 a_hi[2][4], a_lo[2][4], b_hi[4][2], b_lo[4][2];
                #pragma unroll
                for (int ma = 0; ma < 2; ma++) {
                    u32 ad = ah0 + arow + ma * 16 * 80 + kb;
                    ldm4(a_hi[ma][0], a_hi[ma][1], a_hi[ma][2], a_hi[ma][3], ad);
                    ldm4(a_lo[ma][0], a_lo[ma][1], a_lo[ma][2], a_lo[ma][3], ad + AV_APART);
                }
                #pragma unroll
                for (int p = 0; p < 2; p++) {
                    u32 bd = bb0 + brow + p * 16 * 80 + kb;
                    ldm4(b_hi[2*p][0], b_hi[2*p][1], b_hi[2*p+1][0], b_hi[2*p+1][1], bd);
                    ldm4(b_lo[2*p][0], b_lo[2*p][1], b_lo[2*p+1][0], b_lo[2*p+1][1], bd + 5120);
                }
                #pragma unroll
                for (int ma = 0; ma < 2; ma++)
                    #pragma unroll
                    for (int na = 0; na < 4; na++) {
                        mma16816(acc[ma][na], a_hi[ma], b_hi[na]);
                        mma16816(acc[ma][na], a_hi[ma], b_lo[na]);
                        mma16816(acc[ma][na], a_lo[ma], b_hi[na]);
                    }
            }
        }
        __syncthreads();
        if (ck + 3 < 32) issue_loads(ck + 3, s);
    }

    // ---- NEW epilogue: tile max -> scale -> 2-digit int8 ctx ----
    float mx = 0.0f;
    #pragma unroll
    for (int ma = 0; ma < 2; ma++)
        #pragma unroll
        for (int na = 0; na < 4; na++)
            #pragma unroll
            for (int r = 0; r < 4; r++)
                mx = fmaxf(mx, fabsf(acc[ma][na][r]));
    #pragma unroll
    for (int o = 16; o > 0; o >>= 1) mx = fmaxf(mx, __shfl_xor_sync(0xffffffffu, mx, o));

    float* red = (float*)smem;
    if (lane == 0) red[wid] = mx;
    __syncthreads();
    if (tid == 0) {
        float m2 = red[0];
        #pragma unroll
        for (int i = 1; i < 8; i++) m2 = fmaxf(m2, red[i]);
        m2 = fmaxf(m2, 1e-8f);
        red[8] = m2;
        g_cscale[(b8 * 8 + blockIdx.y) * 16 + h] = m2 / 16256.f;
    }
    __syncthreads();
    const float inv = 16256.f / red[8];

    #pragma unroll
    for (int ma = 0; ma < 2; ma++)
        #pragma unroll
        for (int na = 0; na < 4; na++)
            #pragma unroll
            for (int half = 0; half < 2; half++) {
                const int row = bm + wm + ma * 16 + g + half * 8;
                const int col = wn + na * 8 + t * 2;
                const size_t base = ((size_t)(b8 * N_ + row)) * C_ + h * 64 + col;
                signed char a1, a2, b1, b2;
                quant2(acc[ma][na][half * 2 + 0], inv, a1, a2);
                quant2(acc[ma][na][half * 2 + 1], inv, b1, b2);
                g_c1[base] = a1; g_c1[base + 1] = b1;
                g_c2[base] = a2; g_c2[base + 1] = b2;
            }
}

// ---------------------------------------------------------------------------
// INT8 IMMA projection: out = ctx @ w_proj + bias.
// A = ctx digits (per-tile dynamic scale), B = w_projT digits (static R=0.25).
// Tile 128x128, 256 thr, K chunks of 64 s8, 3-stage ring, 4 IMMAs per k32.
// ---------------------------------------------------------------------------
#define IM_PART  10240
#define IM_STAGE (4 * IM_PART)
#define IM_SMEM  (3 * IM_STAGE)   // 122880
#define S_W      (0.25f / 16256.f)

__global__ void __launch_bounds__(256, 1) imma_out(float* __restrict__ out,
                                                   const float* __restrict__ bias)
{
    extern __shared__ char smem[];
    const u32 sb   = smem_u32(smem);
    const int tid  = threadIdx.x;
    const int wid  = tid >> 5, lane = tid & 31;
    const int g    = lane >> 2, t = lane & 3;
    const int bn   = blockIdx.x * 128;
    const int bm   = blockIdx.y * 128;
    const int rb   = blockIdx.y;
    const int wm   = (wid & 1) * 64;
    const int wn   = (wid >> 1) * 32;

    const signed char* A1 = g_c1 + (size_t)bm * C_;
    const signed char* A2 = g_c2 + (size_t)bm * C_;
    const signed char* B1 = g_w1 + (size_t)bn * C_;
    const signed char* B2 = g_w2 + (size_t)bn * C_;

    float facc[4][4][4];
    #pragma unroll
    for (int i = 0; i < 4; i++)
        #pragma unroll
        for (int j = 0; j < 4; j++)
            #pragma unroll
            for (int r = 0; r < 4; r++) facc[i][j][r] = 0.0f;

    auto issue_loads = [&](int ck, int s) {
        const int kofs = ck * 64;
        const u32 base = sb + s * IM_STAGE;
        #pragma unroll
        for (int i = tid; i < 128 * 4; i += 256) {
            int r = i >> 2, sgm = i & 3;
            u32 off = (u32)(r * 80 + sgm * 16);
            const size_t go = (size_t)r * C_ + kofs + sgm * 16;
            CP16(base + off,               A1 + go);
            CP16(base + IM_PART + off,     A2 + go);
            CP16(base + 2 * IM_PART + off, B1 + go);
            CP16(base + 3 * IM_PART + off, B2 + go);
        }
        CP_COMMIT();
    };

    const u32 arow = (u32)((wm + (lane & 15)) * 80 + ((lane >> 4) << 4));
    const u32 brow = (u32)((wn + (lane & 7) + ((lane >> 4) << 3)) * 80 + (((lane >> 3) & 1) << 4));

    issue_loads(0, 0);
    issue_loads(1, 1);
    for (int ck = 0; ck < 16; ck++) {
        const int s = ck % 3;
        if (ck + 2 < 16) { issue_loads(ck + 2, (ck + 2) % 3); CP_WAIT(2); }
        else if (ck + 1 < 16) { CP_WAIT(1); }
        else { CP_WAIT(0); }
        __syncthreads();

        const float sc = g_cscale[rb * 16 + ck] * S_W;
        const float c2 = sc * 16384.f, c1 = sc * 128.f;

        const u32 ab = sb + s * IM_STAGE;
        const u32 bb = ab + 2 * IM_PART;

        u32 bd1[2][4][2], bd2[2][4][2];
        #pragma unroll
        for (int ks = 0; ks < 2; ks++)
            #pragma unroll
            for (int p = 0; p < 2; p++) {
                u32 bd = bb + brow + p * 16 * 80 + ks * 32;
                ldm4(bd1[ks][2*p][0], bd1[ks][2*p][1], bd1[ks][2*p+1][0], bd1[ks][2*p+1][1], bd);
                ldm4(bd2[ks][2*p][0], bd2[ks][2*p][1], bd2[ks][2*p+1][0], bd2[ks][2*p+1][1], bd + IM_PART);
            }

        #pragma unroll
        for (int ma = 0; ma < 4; ma++) {
            u32 ad1[2][4], ad2[2][4];
            #pragma unroll
            for (int ks = 0; ks < 2; ks++) {
                u32 ad = ab + arow + ma * 16 * 80 + ks * 32;
                ldm4(ad1[ks][0], ad1[ks][1], ad1[ks][2], ad1[ks][3], ad);
                ldm4(ad2[ks][0], ad2[ks][1], ad2[ks][2], ad2[ks][3], ad + IM_PART);
            }
            #pragma unroll
            for (int na = 0; na < 4; na++) {
                int P[4] = {0,0,0,0}, Q[4] = {0,0,0,0}, R[4] = {0,0,0,0};
                #pragma unroll
                for (int ks = 0; ks < 2; ks++) {
                    imma16832(P, ad1[ks], bd1[ks][na]);
                    imma16832(Q, ad1[ks], bd2[ks][na]);
                    imma16832(Q, ad2[ks], bd1[ks][na]);
                    imma16832(R, ad2[ks], bd2[ks][na]);
                }
                #pragma unroll
                for (int r = 0; r < 4; r++)
                    facc[ma][na][r] += (float)P[r] * c2 + ((float)Q[r] * c1 + (float)R[r] * sc);
            }
        }
        __syncthreads();
    }

    #pragma unroll
    for (int ma = 0; ma < 4; ma++)
        #pragma unroll
        for (int na = 0; na < 4; na++)
            #pragma unroll
            for (int half = 0; half < 2; half++) {
                const int row = bm + wm + ma * 16 + g + half * 8;
                const int col = bn + wn + na * 8 + t * 2;
                float* dst = out + (size_t)row * C_ + col;
                *(float2*)dst = make_float2(facc[ma][na][half * 2 + 0] + bias[col],
                                            facc[ma][na][half * 2 + 1] + bias[col + 1]);
            }
}

// ---------------- conversion kernels ----------------
__global__ void __launch_bounds__(256) conv_x(const float* __restrict__ s)
{
    int i = blockIdx.x * 256 + threadIdx.x;
    float4 v = ((const float4*)s)[i];
    __nv_bfloat16 h0, l0, h1, l1, h2, l2, h3, l3;
    splitf(v.x, h0, l0); splitf(v.y, h1, l1);
    splitf(v.z, h2, l2); splitf(v.w, h3, l3);
    __nv_bfloat162* hp = (__nv_bfloat162*)g_xh;
    __nv_bfloat162* lp = (__nv_bfloat162*)g_xl;
    hp[i * 2]     = __nv_bfloat162(h0, h1);
    hp[i * 2 + 1] = __nv_bfloat162(h2, h3);
    lp[i * 2]     = __nv_bfloat162(l0, l1);
    lp[i * 2 + 1] = __nv_bfloat162(l2, l3);
}

// w_qkv: transpose + bf16 hi/lo split
__global__ void __launch_bounds__(256) conv_wqkvT(const float* __restrict__ s)
{
    __shared__ float tbuf[32][33];
    const int tx = threadIdx.x & 31, ty = threadIdx.x >> 5;
    const int c0 = blockIdx.x * 32, r0 = blockIdx.y * 32;
    #pragma unroll
    for (int j = 0; j < 4; j++)
        tbuf[ty + j * 8][tx] = s[(size_t)(r0 + ty + j * 8) * QKVC + c0 + tx];
    __syncthreads();
    #pragma unroll
    for (int j = 0; j < 4; j++) {
        int i = ty + j * 8;
        float v = tbuf[tx][i];
        __nv_bfloat16 hh, ll;
        splitf(v, hh, ll);
        size_t idx = (size_t)(c0 + i) * C_ + r0 + tx;
        g_wqh[idx] = hh;
        g_wql[idx] = ll;
    }
}

// w_proj: transpose + 2-digit int8 quantization (static R=0.25)
__global__ void __launch_bounds__(256) conv_wprojQ(const float* __restrict__ s)
{
    __shared__ float tbuf[32][33];
    const int tx = threadIdx.x & 31, ty = threadIdx.x >> 5;
    const int c0 = blockIdx.x * 32, r0 = blockIdx.y * 32;
    #pragma unroll
    for (int j = 0; j < 4; j++)
        tbuf[ty + j * 8][tx] = s[(size_t)(r0 + ty + j * 8) * C_ + c0 + tx];
    __syncthreads();
    #pragma unroll
    for (int j = 0; j < 4; j++) {
        int i = ty + j * 8;
        float v = tbuf[tx][i];
        signed char d1, d2;
        quant2(v, 16256.f / 0.25f, d1, d2);
        size_t idx = (size_t)(c0 + i) * C_ + r0 + tx;
        g_w1[idx] = d1;
        g_w2[idx] = d2;
    }
}

// ---------------------------------------------------------------------------
extern "C" void kernel_launch(void* const* d_in, const int* in_sizes, int n_in,
                              void* d_out, int out_size)
{
    const float* x      = (const float*)d_in[0];
    const float* w_qkv  = (const float*)d_in[1];
    const float* w_proj = (const float*)d_in[2];
    const float* b_proj = (const float*)d_in[3];
    float* out  = (float*)d_out;
    float* attn = out + (size_t)M_ * C_;

    const int S128 = 3 * (2 * 128 * 80 + 2 * 128 * 80);   // 122880

    cudaFuncSetAttribute(qkv_gemm,      cudaFuncAttributeMaxDynamicSharedMemorySize, S128);
    cudaFuncSetAttribute(sscore_kernel, cudaFuncAttributeMaxDynamicSharedMemorySize, SS_SMEM);
    cudaFuncSetAttribute(av_gemm,       cudaFuncAttributeMaxDynamicSharedMemorySize, AV_SMEM);
    cudaFuncSetAttribute(imma_out,      cudaFuncAttributeMaxDynamicSharedMemorySize, IM_SMEM);

    // 1) input conversions
    conv_x<<<M_ * C_ / 1024, 256>>>(x);
    conv_wqkvT<<<dim3(QKVC / 32, C_ / 32), 256>>>(w_qkv);
    conv_wprojQ<<<dim3(C_ / 32, C_ / 32), 256>>>(w_proj);

    // 2) QKV GEMM -> q(scaled)/k/vT splits
    qkv_gemm<<<dim3(QKVC / 128, M_ / 128), 256, S128>>>();

    // 3) S + softmax -> attn fp32
    sscore_kernel<<<BH_ * 32, 256, SS_SMEM>>>(attn);

    // 4) ctx = attn(fp32) @ V -> int8 digits + per-tile scales
    av_gemm<<<dim3(1, N_ / 128, BH_), 256, AV_SMEM>>>(attn);

    // 5) out = ctx @ w_proj + bias (int8 IMMA)
    imma_out<<<dim3(C_ / 128, M_ / 128), 256, IM_SMEM>>>(out, b_proj);
}

// round 9
// speedup vs baseline: 1.4808x; 1.4808x over previous
#include <cuda_runtime.h>
#include <cuda_fp16.h>

typedef unsigned int u32;

#define B_   8
#define N_   1024
#define C_   1024
#define H_   16
#define D_   64
#define M_   (B_ * N_)     // 8192
#define QKVC 3072
#define BH_  (B_ * H_)     // 128

// ---------------- allocation-free scratch (device globals, fp16 splits) ----
__device__ __align__(256) __half g_xh[(size_t)M_ * C_],  g_xl[(size_t)M_ * C_];
__device__ __align__(256) __half g_wqh[(size_t)QKVC * C_];          // lo unused (2-term QKV)
__device__ __align__(256) __half g_wph[(size_t)C_ * C_],  g_wpl[(size_t)C_ * C_];
__device__ __align__(256) __half g_qh[(size_t)BH_ * N_ * D_], g_ql[(size_t)BH_ * N_ * D_];
__device__ __align__(256) __half g_kh[(size_t)BH_ * N_ * D_], g_kl[(size_t)BH_ * N_ * D_];
__device__ __align__(256) __half g_vTh[(size_t)BH_ * D_ * N_], g_vTl[(size_t)BH_ * D_ * N_];
__device__ __align__(256) __half g_ch[(size_t)M_ * C_],  g_cl[(size_t)M_ * C_];

// ---------------- helpers ----------------
__device__ __forceinline__ u32 smem_u32(const void* p) {
    u32 a;
    asm("{ .reg .u64 t; cvta.to.shared.u64 t, %1; cvt.u32.u64 %0, t; }" : "=r"(a) : "l"(p));
    return a;
}
#define CP16(dst, src) \
    asm volatile("cp.async.cg.shared.global [%0], [%1], 16;" :: "r"(dst), "l"(src) : "memory")
#define CP_COMMIT() asm volatile("cp.async.commit_group;" ::: "memory")
#define CP_WAIT(n)  asm volatile("cp.async.wait_group %0;" :: "n"(n) : "memory")

__device__ __forceinline__ void ldm4(u32& r0, u32& r1, u32& r2, u32& r3, u32 a) {
    asm volatile("ldmatrix.sync.aligned.m8n8.x4.shared.b16 {%0,%1,%2,%3}, [%4];"
        : "=r"(r0), "=r"(r1), "=r"(r2), "=r"(r3) : "r"(a));
}
__device__ __forceinline__ void mma16816(float* c, const u32* a, const u32* b) {
    asm volatile(
        "mma.sync.aligned.m16n8k16.row.col.f32.f16.f16.f32 "
        "{%0,%1,%2,%3}, {%4,%5,%6,%7}, {%8,%9}, {%0,%1,%2,%3};"
        : "+f"(c[0]), "+f"(c[1]), "+f"(c[2]), "+f"(c[3])
        : "r"(a[0]), "r"(a[1]), "r"(a[2]), "r"(a[3]), "r"(b[0]), "r"(b[1]));
}
__device__ __forceinline__ void splith(float v, __half& h, __half& l) {
    h = __float2half(v);
    l = __float2half(v - __half2float(h));
}

// ---------------------------------------------------------------------------
// QKV GEMM: 2-term fp16 split (ah*bh + al*bh). 256 thr, MA4 NA4, 3-stage ring.
// ---------------------------------------------------------------------------
#define QK_PART  10240
#define QK_STAGE (3 * QK_PART)
#define QK_SMEM  (3 * QK_STAGE)   // 92160

__global__ void __launch_bounds__(256, 1) qkv_gemm()
{
    constexpr int NC = 32;
    constexpr int MA = 4;
    constexpr int NA = 4;

    extern __shared__ char smem[];
    const u32 sb   = smem_u32(smem);
    const int tid  = threadIdx.x;
    const int wid  = tid >> 5, lane = tid & 31;
    const int g    = lane >> 2, t = lane & 3;
    const int bn   = blockIdx.x * 128;
    const int bm   = blockIdx.y * 128;
    const int wm   = (wid & 1) * 64;
    const int wn   = (wid >> 1) * 32;

    const __half *Ah = g_xh + (size_t)bm * C_, *Al = g_xl + (size_t)bm * C_;
    const __half *Bh = g_wqh + (size_t)bn * C_;

    float acc[MA][NA][4];
    #pragma unroll
    for (int i = 0; i < MA; i++)
        #pragma unroll
        for (int j = 0; j < NA; j++)
            #pragma unroll
            for (int r = 0; r < 4; r++) acc[i][j][r] = 0.0f;

    auto issue_loads = [&](int ck, int s) {
        const int kofs = ck * 32;
        const u32 base = sb + s * QK_STAGE;
        #pragma unroll
        for (int i = tid; i < 128 * 4; i += 256) {
            int r = i >> 2, sgm = i & 3;
            u32 off = (u32)(r * 80 + sgm * 16);
            const size_t go = (size_t)r * C_ + kofs + sgm * 8;
            CP16(base + off,               Ah + go);
            CP16(base + QK_PART + off,     Al + go);
            CP16(base + 2 * QK_PART + off, Bh + go);
        }
        CP_COMMIT();
    };

    const u32 arow = (u32)((wm + (lane & 15)) * 80 + ((lane >> 4) << 4));
    const u32 brow = (u32)((wn + (lane & 7) + ((lane >> 4) << 3)) * 80 + (((lane >> 3) & 1) << 4));

    auto do_compute = [&](int s) {
        const u32 abase = sb + s * QK_STAGE;
        const u32 bbase = abase + 2 * QK_PART;
        #pragma unroll
        for (int ks = 0; ks < 2; ks++) {
            const u32 kb = ks * 32;
            u32 a_hi[MA][4], a_lo[MA][4], b_hi[NA][2];
            #pragma unroll
            for (int ma = 0; ma < MA; ma++) {
                u32 ad = abase + arow + ma * 16 * 80 + kb;
                ldm4(a_hi[ma][0], a_hi[ma][1], a_hi[ma][2], a_hi[ma][3], ad);
                ldm4(a_lo[ma][0], a_lo[ma][1], a_lo[ma][2], a_lo[ma][3], ad + QK_PART);
            }
            #pragma unroll
            for (int p = 0; p < NA / 2; p++) {
                u32 bd = bbase + brow + p * 16 * 80 + kb;
                ldm4(b_hi[2*p][0], b_hi[2*p][1], b_hi[2*p+1][0], b_hi[2*p+1][1], bd);
            }
            #pragma unroll
            for (int ma = 0; ma < MA; ma++)
                #pragma unroll
                for (int na = 0; na < NA; na++) {
                    mma16816(acc[ma][na], a_hi[ma], b_hi[na]);
                    mma16816(acc[ma][na], a_lo[ma], b_hi[na]);
                }
        }
    };

    issue_loads(0, 0);
    issue_loads(1, 1);
    for (int ck = 0; ck < NC; ck++) {
        const int s = ck % 3;
        if (ck + 2 < NC) { issue_loads(ck + 2, (ck + 2) % 3); CP_WAIT(2); }
        else if (ck + 1 < NC) { CP_WAIT(1); }
        else { CP_WAIT(0); }
        __syncthreads();
        do_compute(s);
        __syncthreads();
    }

    // ---- epilogue: scatter q(scaled)/k/vT fp16 hi+lo ----
    #pragma unroll
    for (int ma = 0; ma < MA; ma++)
        #pragma unroll
        for (int na = 0; na < NA; na++)
            #pragma unroll
            for (int half = 0; half < 2; half++) {
                const int row = bm + wm + ma * 16 + g + half * 8;
                const int col = bn + wn + na * 8 + t * 2;
                float v0 = acc[ma][na][half * 2 + 0];
                float v1 = acc[ma][na][half * 2 + 1];

                const int which = col >> 10;
                const int c     = col & 1023;
                const int h     = c >> 6;
                const int d0    = c & 63;
                const int b8    = row >> 10;
                const int n     = row & 1023;
                const int bh    = b8 * H_ + h;
                if (which == 0) {
                    __half h0, l0, h1, l1;
                    splith(v0 * 0.125f, h0, l0); splith(v1 * 0.125f, h1, l1);
                    const size_t base = ((size_t)bh * N_ + n) * D_ + d0;
                    *(__half2*)(g_qh + base) = __halves2half2(h0, h1);
                    *(__half2*)(g_ql + base) = __halves2half2(l0, l1);
                } else if (which == 1) {
                    __half h0, l0, h1, l1;
                    splith(v0, h0, l0); splith(v1, h1, l1);
                    const size_t base = ((size_t)bh * N_ + n) * D_ + d0;
                    *(__half2*)(g_kh + base) = __halves2half2(h0, h1);
                    *(__half2*)(g_kl + base) = __halves2half2(l0, l1);
                } else {
                    __half h0, l0, h1, l1;
                    splith(v0, h0, l0); splith(v1, h1, l1);
                    const size_t vb = (size_t)bh * D_ * N_ + n;
                    g_vTh[vb + (size_t)d0 * N_]       = h0;
                    g_vTh[vb + (size_t)(d0 + 1) * N_] = h1;
                    g_vTl[vb + (size_t)d0 * N_]       = l0;
                    g_vTl[vb + (size_t)(d0 + 1) * N_] = l1;
                }
            }
}

// ---------------------------------------------------------------------------
// Fused S = qk^T -> softmax -> attn fp32 out (3-term fp16, structure = r7).
// ---------------------------------------------------------------------------
#define Q_OFF  0
#define QL_OFF 4608
#define K_OFF  9216
#define KSTG   36864
#define KL_OFF 18432
#define S_OFF  82944
#define S_PIT  4144
#define SS_SMEM (S_OFF + 32 * S_PIT)   // 215552

__global__ void __launch_bounds__(256, 1) sscore_kernel(float* __restrict__ attn)
{
    extern __shared__ char smem[];
    const u32 sb   = smem_u32(smem);
    const int tid  = threadIdx.x;
    const int wid  = tid >> 5, lane = tid & 31;
    const int g    = lane >> 2, t = lane & 3;

    const int bh   = blockIdx.x >> 5;
    const int row0 = (blockIdx.x & 31) * 32;
    const int wm   = (wid & 1) * 16;
    const int wn   = (wid >> 1) * 32;

    const __half* Qh = g_qh + ((size_t)bh * N_ + row0) * D_;
    const __half* Ql = g_ql + ((size_t)bh * N_ + row0) * D_;
    const __half* Kh = g_kh + (size_t)bh * N_ * D_;
    const __half* Kl = g_kl + (size_t)bh * N_ * D_;

    {
        int r = tid >> 3, sgm = tid & 7;
        u32 off = (u32)(r * 144 + sgm * 16);
        *(float4*)(smem + Q_OFF + off)  = *(const float4*)(Qh + r * D_ + sgm * 8);
        *(float4*)(smem + QL_OFF + off) = *(const float4*)(Ql + r * D_ + sgm * 8);
    }

    auto issueK = [&](int c, int s) {
        const u32 base = sb + K_OFF + s * KSTG;
        const size_t ko = (size_t)c * 128 * D_;
        #pragma unroll
        for (int i = tid; i < 128 * 8; i += 256) {
            int r = i >> 3, sgm = i & 7;
            u32 off = (u32)(r * 144 + sgm * 16);
            CP16(base + off,          Kh + ko + r * D_ + sgm * 8);
            CP16(base + KL_OFF + off, Kl + ko + r * D_ + sgm * 8);
        }
        CP_COMMIT();
    };

    const u32 arow = (u32)((wm + (lane & 15)) * 144 + ((lane >> 4) << 4));
    const u32 brow = (u32)((wn + (lane & 7) + ((lane >> 4) << 3)) * 144 + (((lane >> 3) & 1) << 4));

    issueK(0, 0);
    issueK(1, 1);
    for (int c = 0; c < 8; c++) {
        if (c < 7) CP_WAIT(1); else CP_WAIT(0);
        __syncthreads();

        const u32 kb0 = sb + K_OFF + (c & 1) * KSTG;
        float acc[4][4];
        #pragma unroll
        for (int j = 0; j < 4; j++)
            #pragma unroll
            for (int r = 0; r < 4; r++) acc[j][r] = 0.0f;

        #pragma unroll
        for (int ks = 0; ks < 4; ks++) {
            const u32 kb = ks * 32;
            u32 a_hi[4], a_lo[4], b_hi[4][2], b_lo[4][2];
            u32 ad = sb + Q_OFF + arow + kb;
            ldm4(a_hi[0], a_hi[1], a_hi[2], a_hi[3], ad);
            ldm4(a_lo[0], a_lo[1], a_lo[2], a_lo[3], ad + QL_OFF);
            #pragma unroll
            for (int p = 0; p < 2; p++) {
                u32 bd = kb0 + brow + p * 16 * 144 + kb;
                ldm4(b_hi[2*p][0], b_hi[2*p][1], b_hi[2*p+1][0], b_hi[2*p+1][1], bd);
                ldm4(b_lo[2*p][0], b_lo[2*p][1], b_lo[2*p+1][0], b_lo[2*p+1][1], bd + KL_OFF);
            }
            #pragma unroll
            for (int na = 0; na < 4; na++) {
                mma16816(acc[na], a_hi, b_hi[na]);
                mma16816(acc[na], a_hi, b_lo[na]);
                mma16816(acc[na], a_lo, b_hi[na]);
            }
        }

        #pragma unroll
        for (int na = 0; na < 4; na++)
            #pragma unroll
            for (int half = 0; half < 2; half++) {
                int row = wm + g + half * 8;
                int col = c * 128 + wn + na * 8 + t * 2;
                *(float2*)(smem + S_OFF + row * S_PIT + col * 4) =
                    make_float2(acc[na][half * 2], acc[na][half * 2 + 1]);
            }

        __syncthreads();
        if (c + 2 < 8) issueK(c + 2, c & 1);
    }

    #pragma unroll
    for (int rr = 0; rr < 4; rr++) {
        const int r = wid * 4 + rr;
        const float* Srow = (const float*)(smem + S_OFF + r * S_PIT);
        float4 f[8];
        float m = -1e30f;
        #pragma unroll
        for (int i = 0; i < 8; i++) {
            f[i] = *(const float4*)(Srow + (lane + i * 32) * 4);
            m = fmaxf(m, fmaxf(fmaxf(f[i].x, f[i].y), fmaxf(f[i].z, f[i].w)));
        }
        #pragma unroll
        for (int o = 16; o > 0; o >>= 1) m = fmaxf(m, __shfl_xor_sync(0xffffffffu, m, o));
        float s = 0.0f;
        #pragma unroll
        for (int i = 0; i < 8; i++) {
            f[i].x = __expf(f[i].x - m); f[i].y = __expf(f[i].y - m);
            f[i].z = __expf(f[i].z - m); f[i].w = __expf(f[i].w - m);
            s += f[i].x + f[i].y + f[i].z + f[i].w;
        }
        #pragma unroll
        for (int o = 16; o > 0; o >>= 1) s += __shfl_xor_sync(0xffffffffu, s, o);
        const float inv = 1.0f / s;

        float* ap = attn + ((size_t)bh * N_ + row0 + r) * N_;
        #pragma unroll
        for (int i = 0; i < 8; i++) {
            *(float4*)(ap + (lane + i * 32) * 4) =
                make_float4(f[i].x * inv, f[i].y * inv, f[i].z * inv, f[i].w * inv);
        }
    }
}

// ---------------------------------------------------------------------------
// AV GEMM: ctx = P @ V, P fp32 from attn, split to fp16 hi/lo in smem (3-term).
// ---------------------------------------------------------------------------
#define AV_ASTG   18432
#define AV_AH_OFF (3 * AV_ASTG)
#define AV_APART  10240
#define AV_B_OFF  (AV_AH_OFF + 2 * AV_APART)
#define AV_BSTG   10240
#define AV_SMEM   (AV_B_OFF + 3 * AV_BSTG)         // 106496

__global__ void __launch_bounds__(256, 1) av_gemm(const float* __restrict__ attn)
{
    extern __shared__ char smem[];
    const u32 sb   = smem_u32(smem);
    const int tid  = threadIdx.x;
    const int wid  = tid >> 5, lane = tid & 31;
    const int g    = lane >> 2, t = lane & 3;

    const int bm = blockIdx.y * 128;
    const int z  = blockIdx.z;
    const int b8 = z >> 4, h = z & 15;
    const int wm = (wid & 3) * 32;
    const int wn = (wid >> 2) * 32;

    const float* Ap = attn + (size_t)z * N_ * N_ + (size_t)bm * N_;
    const __half* Vh = g_vTh + (size_t)z * D_ * N_;
    const __half* Vl = g_vTl + (size_t)z * D_ * N_;

    float acc[2][4][4];
    #pragma unroll
    for (int i = 0; i < 2; i++)
        #pragma unroll
        for (int j = 0; j < 4; j++)
            #pragma unroll
            for (int r = 0; r < 4; r++) acc[i][j][r] = 0.0f;

    auto issue_loads = [&](int ck, int s) {
        const int kofs = ck * 32;
        const u32 abase = sb + s * AV_ASTG;
        #pragma unroll
        for (int i = tid; i < 128 * 8; i += 256) {
            int r = i >> 3, sgm = i & 7;
            CP16(abase + (u32)(r * 144 + sgm * 16), Ap + (size_t)r * N_ + kofs + sgm * 4);
        }
        const u32 bbase = sb + AV_B_OFF + s * AV_BSTG;
        #pragma unroll
        for (int i = tid; i < 64 * 4; i += 256) {
            int r = i >> 2, sgm = i & 3;
            u32 off = (u32)(r * 80 + sgm * 16);
            CP16(bbase + off,        Vh + (size_t)r * N_ + kofs + sgm * 8);
            CP16(bbase + 5120 + off, Vl + (size_t)r * N_ + kofs + sgm * 8);
        }
        CP_COMMIT();
    };

    const u32 arow = (u32)((wm + (lane & 15)) * 80 + ((lane >> 4) << 4));
    const u32 brow = (u32)((wn + (lane & 7) + ((lane >> 4) << 3)) * 80 + (((lane >> 3) & 1) << 4));

    issue_loads(0, 0);
    issue_loads(1, 1);
    issue_loads(2, 2);
    for (int ck = 0; ck < 32; ck++) {
        const int s = ck % 3;
        if (ck <= 29) CP_WAIT(2);
        else if (ck == 30) CP_WAIT(1);
        else CP_WAIT(0);
        __syncthreads();

        {
            const char* src = smem + s * AV_ASTG + (tid >> 1) * 144 + (tid & 1) * 64;
            float4 v0 = *(const float4*)(src);
            float4 v1 = *(const float4*)(src + 16);
            float4 v2 = *(const float4*)(src + 32);
            float4 v3 = *(const float4*)(src + 48);
            float fv[16] = { v0.x,v0.y,v0.z,v0.w, v1.x,v1.y,v1.z,v1.w,
                             v2.x,v2.y,v2.z,v2.w, v3.x,v3.y,v3.z,v3.w };
            u32 hw[8], lw[8];
            #pragma unroll
            for (int p = 0; p < 8; p++) {
                __half h0, l0, h1, l1;
                splith(fv[2*p],   h0, l0);
                splith(fv[2*p+1], h1, l1);
                __half2 hh = __halves2half2(h0, h1), ll = __halves2half2(l0, l1);
                hw[p] = *(u32*)&hh; lw[p] = *(u32*)&ll;
            }
            char* dh = smem + AV_AH_OFF + (tid >> 1) * 80 + (tid & 1) * 32;
            char* dl = dh + AV_APART;
            *(uint4*)dh        = make_uint4(hw[0], hw[1], hw[2], hw[3]);
            *(uint4*)(dh + 16) = make_uint4(hw[4], hw[5], hw[6], hw[7]);
            *(uint4*)dl        = make_uint4(lw[0], lw[1], lw[2], lw[3]);
            *(uint4*)(dl + 16) = make_uint4(lw[4], lw[5], lw[6], lw[7]);
        }
        __syncthreads();

        {
            const u32 ah0 = sb + AV_AH_OFF;
            const u32 bb0 = sb + AV_B_OFF + s * AV_BSTG;
            #pragma unroll
            for (int ks = 0; ks < 2; ks++) {
                const u32 kb = ks * 32;
                u32 a_hi[2][4], a_lo[2][4], b_hi[4][2], b_lo[4][2];
                #pragma unroll
                for (int ma = 0; ma < 2; ma++) {
                    u32 ad = ah0 + arow + ma * 16 * 80 + kb;
                    ldm4(a_hi[ma][0], a_hi[ma][1], a_hi[ma][2], a_hi[ma][3], ad);
                    ldm4(a_lo[ma][0], a_lo[ma][1], a_lo[ma][2], a_lo[ma][3], ad + AV_APART);
                }
                #pragma unroll
                for (int p = 0; p < 2; p++) {
                    u32 bd = bb0 + brow + p * 16 * 80 + kb;
                    ldm4(b_hi[2*p][0], b_hi[2*p][1], b_hi[2*p+1][0], b_hi[2*p+1][1], bd);
                    ldm4(b_lo[2*p][0], b_lo[2*p][1], b_lo[2*p+1][0], b_lo[2*p+1][1], bd + 5120);
                }
                #pragma unroll
                for (int ma = 0; ma < 2; ma++)
                    #pragma unroll
                    for (int na = 0; na < 4; na++) {
                        mma16816(acc[ma][na], a_hi[ma], b_hi[na]);
                        mma16816(acc[ma][na], a_hi[ma], b_lo[na]);
                        mma16816(acc[ma][na], a_lo[ma], b_hi[na]);
                    }
            }
        }
        __syncthreads();
        if (ck + 3 < 32) issue_loads(ck + 3, s);
    }

    // epilogue: ctx split -> g_ch/g_cl (fp16)
    #pragma unroll
    for (int ma = 0; ma < 2; ma++)
        #pragma unroll
        for (int na = 0; na < 4; na++)
            #pragma unroll
            for (int half = 0; half < 2; half++) {
                const int row = bm + wm + ma * 16 + g + half * 8;
                const int col = wn + na * 8 + t * 2;
                const size_t base = ((size_t)(b8 * N_ + row)) * C_ + h * 64 + col;
                __half h0, l0, h1, l1;
                splith(acc[ma][na][half * 2 + 0], h0, l0);
                splith(acc[ma][na][half * 2 + 1], h1, l1);
                *(__half2*)(g_ch + base) = __halves2half2(h0, h1);
                *(__half2*)(g_cl + base) = __halves2half2(l0, l1);
            }
}

// ---------------------------------------------------------------------------
// Projection GEMM: out = ctx @ w_proj + bias (3-term fp16, r7 structure).
// ---------------------------------------------------------------------------
#define PJ_PART  10240
#define PJ_STAGE (4 * PJ_PART)
#define PJ_SMEM  (3 * PJ_STAGE)   // 122880

__global__ void __launch_bounds__(256, 1) proj_gemm(float* __restrict__ out,
                                                    const float* __restrict__ bias)
{
    constexpr int NC = 32;
    constexpr int MA = 4;
    constexpr int NA = 4;

    extern __shared__ char smem[];
    const u32 sb   = smem_u32(smem);
    const int tid  = threadIdx.x;
    const int wid  = tid >> 5, lane = tid & 31;
    const int g    = lane >> 2, t = lane & 3;
    const int bn   = blockIdx.x * 128;
    const int bm   = blockIdx.y * 128;
    const int wm   = (wid & 1) * 64;
    const int wn   = (wid >> 1) * 32;

    const __half *Ah = g_ch + (size_t)bm * C_, *Al = g_cl + (size_t)bm * C_;
    const __half *Bh = g_wph + (size_t)bn * C_, *Bl = g_wpl + (size_t)bn * C_;

    float acc[MA][NA][4];
    #pragma unroll
    for (int i = 0; i < MA; i++)
        #pragma unroll
        for (int j = 0; j < NA; j++)
            #pragma unroll
            for (int r = 0; r < 4; r++) acc[i][j][r] = 0.0f;

    auto issue_loads = [&](int ck, int s) {
        const int kofs = ck * 32;
        const u32 base = sb + s * PJ_STAGE;
        #pragma unroll
        for (int i = tid; i < 128 * 4; i += 256) {
            int r = i >> 2, sgm = i & 3;
            u32 off = (u32)(r * 80 + sgm * 16);
            const size_t go = (size_t)r * C_ + kofs + sgm * 8;
            CP16(base + off,               Ah + go);
            CP16(base + PJ_PART + off,     Al + go);
            CP16(base + 2 * PJ_PART + off, Bh + go);
            CP16(base + 3 * PJ_PART + off, Bl + go);
        }
        CP_COMMIT();
    };

    const u32 arow = (u32)((wm + (lane & 15)) * 80 + ((lane >> 4) << 4));
    const u32 brow = (u32)((wn + (lane & 7) + ((lane >> 4) << 3)) * 80 + (((lane >> 3) & 1) << 4));

    auto do_compute = [&](int s) {
        const u32 abase = sb + s * PJ_STAGE;
        const u32 bbase = abase + 2 * PJ_PART;
        #pragma unroll
        for (int ks = 0; ks < 2; ks++) {
            const u32 kb = ks * 32;
            u32 a_hi[MA][4], a_lo[MA][4], b_hi[NA][2], b_lo[NA][2];
            #pragma unroll
            for (int ma = 0; ma < MA; ma++) {
                u32 ad = abase + arow + ma * 16 * 80 + kb;
                ldm4(a_hi[ma][0], a_hi[ma][1], a_hi[ma][2], a_hi[ma][3], ad);
                ldm4(a_lo[ma][0], a_lo[ma][1], a_lo[ma][2], a_lo[ma][3], ad + PJ_PART);
            }
            #pragma unroll
            for (int p = 0; p < NA / 2; p++) {
                u32 bd = bbase + brow + p * 16 * 80 + kb;
                ldm4(b_hi[2*p][0], b_hi[2*p][1], b_hi[2*p+1][0], b_hi[2*p+1][1], bd);
                ldm4(b_lo[2*p][0], b_lo[2*p][1], b_lo[2*p+1][0], b_lo[2*p+1][1], bd + PJ_PART);
            }
            #pragma unroll
            for (int ma = 0; ma < MA; ma++)
                #pragma unroll
                for (int na = 0; na < NA; na++) {
                    mma16816(acc[ma][na], a_hi[ma], b_hi[na]);
                    mma16816(acc[ma][na], a_hi[ma], b_lo[na]);
                    mma16816(acc[ma][na], a_lo[ma], b_hi[na]);
                }
        }
    };

    issue_loads(0, 0);
    issue_loads(1, 1);
    for (int ck = 0; ck < NC; ck++) {
        const int s = ck % 3;
        if (ck + 2 < NC) { issue_loads(ck + 2, (ck + 2) % 3); CP_WAIT(2); }
        else if (ck + 1 < NC) { CP_WAIT(1); }
        else { CP_WAIT(0); }
        __syncthreads();
        do_compute(s);
        __syncthreads();
    }

    #pragma unroll
    for (int ma = 0; ma < MA; ma++)
        #pragma unroll
        for (int na = 0; na < NA; na++)
            #pragma unroll
            for (int half = 0; half < 2; half++) {
                const int row = bm + wm + ma * 16 + g + half * 8;
                const int col = bn + wn + na * 8 + t * 2;
                float* dst = out + (size_t)row * C_ + col;
                *(float2*)dst = make_float2(acc[ma][na][half * 2 + 0] + bias[col],
                                            acc[ma][na][half * 2 + 1] + bias[col + 1]);
            }
}

// ---------------- conversion kernels ----------------
__global__ void __launch_bounds__(256) conv_x(const float* __restrict__ s)
{
    int i = blockIdx.x * 256 + threadIdx.x;
    float4 v = ((const float4*)s)[i];
    __half h0, l0, h1, l1, h2, l2, h3, l3;
    splith(v.x, h0, l0); splith(v.y, h1, l1);
    splith(v.z, h2, l2); splith(v.w, h3, l3);
    __half2* hp = (__half2*)g_xh;
    __half2* lp = (__half2*)g_xl;
    hp[i * 2]     = __halves2half2(h0, h1);
    hp[i * 2 + 1] = __halves2half2(h2, h3);
    lp[i * 2]     = __halves2half2(l0, l1);
    lp[i * 2 + 1] = __halves2half2(l2, l3);
}

// w_qkv: transpose + fp16 hi only (2-term QKV never reads lo)
__global__ void __launch_bounds__(256) conv_wqkvT(const float* __restrict__ s)
{
    __shared__ float tbuf[32][33];
    const int tx = threadIdx.x & 31, ty = threadIdx.x >> 5;
    const int c0 = blockIdx.x * 32, r0 = blockIdx.y * 32;
    #pragma unroll
    for (int j = 0; j < 4; j++)
        tbuf[ty + j * 8][tx] = s[(size_t)(r0 + ty + j * 8) * QKVC + c0 + tx];
    __syncthreads();
    #pragma unroll
    for (int j = 0; j < 4; j++) {
        int i = ty + j * 8;
        g_wqh[(size_t)(c0 + i) * C_ + r0 + tx] = __float2half(tbuf[tx][i]);
    }
}

// w_proj: transpose + fp16 hi/lo split
__global__ void __launch_bounds__(256) conv_wprojT(const float* __restrict__ s)
{
    __shared__ float tbuf[32][33];
    const int tx = threadIdx.x & 31, ty = threadIdx.x >> 5;
    const int c0 = blockIdx.x * 32, r0 = blockIdx.y * 32;
    #pragma unroll
    for (int j = 0; j < 4; j++)
        tbuf[ty + j * 8][tx] = s[(size_t)(r0 + ty + j * 8) * C_ + c0 + tx];
    __syncthreads();
    #pragma unroll
    for (int j = 0; j < 4; j++) {
        int i = ty + j * 8;
        __half hh, ll;
        splith(tbuf[tx][i], hh, ll);
        size_t idx = (size_t)(c0 + i) * C_ + r0 + tx;
        g_wph[idx] = hh;
        g_wpl[idx] = ll;
    }
}

// ---------------------------------------------------------------------------
extern "C" void kernel_launch(void* const* d_in, const int* in_sizes, int n_in,
                              void* d_out, int out_size)
{
    const float* x      = (const float*)d_in[0];
    const float* w_qkv  = (const float*)d_in[1];
    const float* w_proj = (const float*)d_in[2];
    const float* b_proj = (const float*)d_in[3];
    float* out  = (float*)d_out;
    float* attn = out + (size_t)M_ * C_;

    cudaFuncSetAttribute(qkv_gemm,      cudaFuncAttributeMaxDynamicSharedMemorySize, QK_SMEM);
    cudaFuncSetAttribute(sscore_kernel, cudaFuncAttributeMaxDynamicSharedMemorySize, SS_SMEM);
    cudaFuncSetAttribute(av_gemm,       cudaFuncAttributeMaxDynamicSharedMemorySize, AV_SMEM);
    cudaFuncSetAttribute(proj_gemm,     cudaFuncAttributeMaxDynamicSharedMemorySize, PJ_SMEM);

    // 1) input conversions
    conv_x<<<M_ * C_ / 1024, 256>>>(x);
    conv_wqkvT<<<dim3(QKVC / 32, C_ / 32), 256>>>(w_qkv);
    conv_wprojT<<<dim3(C_ / 32, C_ / 32), 256>>>(w_proj);

    // 2) QKV GEMM (2-term fp16) -> q(scaled)/k/vT splits
    qkv_gemm<<<dim3(QKVC / 128, M_ / 128), 256, QK_SMEM>>>();

    // 3) S + softmax -> attn fp32 (3-term fp16)
    sscore_kernel<<<BH_ * 32, 256, SS_SMEM>>>(attn);

    // 4) ctx = attn(fp32) @ V (3-term fp16)
    av_gemm<<<dim3(1, N_ / 128, BH_), 256, AV_SMEM>>>(attn);

    // 5) out = ctx @ w_proj + bias (3-term fp16)
    proj_gemm<<<dim3(C_ / 128, M_ / 128), 256, PJ_SMEM>>>(out, b_proj);
}

// round 10
// speedup vs baseline: 1.7038x; 1.1506x over previous
#include <cuda_runtime.h>
#include <cuda_fp16.h>

typedef unsigned int u32;

#define B_   8
#define N_   1024
#define C_   1024
#define H_   16
#define D_   64
#define M_   (B_ * N_)     // 8192
#define QKVC 3072
#define BH_  (B_ * H_)     // 128

// ---------------- allocation-free scratch (device globals, fp16) ----------
__device__ __align__(256) __half g_xh[(size_t)M_ * C_],  g_xl[(size_t)M_ * C_];
__device__ __align__(256) __half g_wqh[(size_t)QKVC * C_];
__device__ __align__(256) __half g_wph[(size_t)C_ * C_];
__device__ __align__(256) __half g_qh[(size_t)BH_ * N_ * D_], g_ql[(size_t)BH_ * N_ * D_];
__device__ __align__(256) __half g_kh[(size_t)BH_ * N_ * D_];
__device__ __align__(256) __half g_vTh[(size_t)BH_ * D_ * N_];
__device__ __align__(256) __half g_ch[(size_t)M_ * C_],  g_cl[(size_t)M_ * C_];

// ---------------- helpers ----------------
__device__ __forceinline__ u32 smem_u32(const void* p) {
    u32 a;
    asm("{ .reg .u64 t; cvta.to.shared.u64 t, %1; cvt.u32.u64 %0, t; }" : "=r"(a) : "l"(p));
    return a;
}
#define CP16(dst, src) \
    asm volatile("cp.async.cg.shared.global [%0], [%1], 16;" :: "r"(dst), "l"(src) : "memory")
#define CP_COMMIT() asm volatile("cp.async.commit_group;" ::: "memory")
#define CP_WAIT(n)  asm volatile("cp.async.wait_group %0;" :: "n"(n) : "memory")

__device__ __forceinline__ void ldm4(u32& r0, u32& r1, u32& r2, u32& r3, u32 a) {
    asm volatile("ldmatrix.sync.aligned.m8n8.x4.shared.b16 {%0,%1,%2,%3}, [%4];"
        : "=r"(r0), "=r"(r1), "=r"(r2), "=r"(r3) : "r"(a));
}
__device__ __forceinline__ void mma16816(float* c, const u32* a, const u32* b) {
    asm volatile(
        "mma.sync.aligned.m16n8k16.row.col.f32.f16.f16.f32 "
        "{%0,%1,%2,%3}, {%4,%5,%6,%7}, {%8,%9}, {%0,%1,%2,%3};"
        : "+f"(c[0]), "+f"(c[1]), "+f"(c[2]), "+f"(c[3])
        : "r"(a[0]), "r"(a[1]), "r"(a[2]), "r"(a[3]), "r"(b[0]), "r"(b[1]));
}
__device__ __forceinline__ void splith(float v, __half& h, __half& l) {
    h = __float2half(v);
    l = __float2half(v - __half2float(h));
}

// ---------------------------------------------------------------------------
// QKV GEMM: 2-term fp16 ((ah+al)*bh). 256 thr, MA4 NA4, 3-stage ring.
// Epilogue: q hi+lo (scaled), k hi only, vT hi only.
// ---------------------------------------------------------------------------
#define QK_PART  10240
#define QK_STAGE (3 * QK_PART)
#define QK_SMEM  (3 * QK_STAGE)   // 92160

__global__ void __launch_bounds__(256, 1) qkv_gemm()
{
    constexpr int NC = 32;
    constexpr int MA = 4;
    constexpr int NA = 4;

    extern __shared__ char smem[];
    const u32 sb   = smem_u32(smem);
    const int tid  = threadIdx.x;
    const int wid  = tid >> 5, lane = tid & 31;
    const int g    = lane >> 2, t = lane & 3;
    const int bn   = blockIdx.x * 128;
    const int bm   = blockIdx.y * 128;
    const int wm   = (wid & 1) * 64;
    const int wn   = (wid >> 1) * 32;

    const __half *Ah = g_xh + (size_t)bm * C_, *Al = g_xl + (size_t)bm * C_;
    const __half *Bh = g_wqh + (size_t)bn * C_;

    float acc[MA][NA][4];
    #pragma unroll
    for (int i = 0; i < MA; i++)
        #pragma unroll
        for (int j = 0; j < NA; j++)
            #pragma unroll
            for (int r = 0; r < 4; r++) acc[i][j][r] = 0.0f;

    auto issue_loads = [&](int ck, int s) {
        const int kofs = ck * 32;
        const u32 base = sb + s * QK_STAGE;
        #pragma unroll
        for (int i = tid; i < 128 * 4; i += 256) {
            int r = i >> 2, sgm = i & 3;
            u32 off = (u32)(r * 80 + sgm * 16);
            const size_t go = (size_t)r * C_ + kofs + sgm * 8;
            CP16(base + off,               Ah + go);
            CP16(base + QK_PART + off,     Al + go);
            CP16(base + 2 * QK_PART + off, Bh + go);
        }
        CP_COMMIT();
    };

    const u32 arow = (u32)((wm + (lane & 15)) * 80 + ((lane >> 4) << 4));
    const u32 brow = (u32)((wn + (lane & 7) + ((lane >> 4) << 3)) * 80 + (((lane >> 3) & 1) << 4));

    auto do_compute = [&](int s) {
        const u32 abase = sb + s * QK_STAGE;
        const u32 bbase = abase + 2 * QK_PART;
        #pragma unroll
        for (int ks = 0; ks < 2; ks++) {
            const u32 kb = ks * 32;
            u32 a_hi[MA][4], a_lo[MA][4], b_hi[NA][2];
            #pragma unroll
            for (int ma = 0; ma < MA; ma++) {
                u32 ad = abase + arow + ma * 16 * 80 + kb;
                ldm4(a_hi[ma][0], a_hi[ma][1], a_hi[ma][2], a_hi[ma][3], ad);
                ldm4(a_lo[ma][0], a_lo[ma][1], a_lo[ma][2], a_lo[ma][3], ad + QK_PART);
            }
            #pragma unroll
            for (int p = 0; p < NA / 2; p++) {
                u32 bd = bbase + brow + p * 16 * 80 + kb;
                ldm4(b_hi[2*p][0], b_hi[2*p][1], b_hi[2*p+1][0], b_hi[2*p+1][1], bd);
            }
            #pragma unroll
            for (int ma = 0; ma < MA; ma++)
                #pragma unroll
                for (int na = 0; na < NA; na++) {
                    mma16816(acc[ma][na], a_hi[ma], b_hi[na]);
                    mma16816(acc[ma][na], a_lo[ma], b_hi[na]);
                }
        }
    };

    issue_loads(0, 0);
    issue_loads(1, 1);
    for (int ck = 0; ck < NC; ck++) {
        const int s = ck % 3;
        if (ck + 2 < NC) { issue_loads(ck + 2, (ck + 2) % 3); CP_WAIT(2); }
        else if (ck + 1 < NC) { CP_WAIT(1); }
        else { CP_WAIT(0); }
        __syncthreads();
        do_compute(s);
        __syncthreads();
    }

    // ---- epilogue ----
    #pragma unroll
    for (int ma = 0; ma < MA; ma++)
        #pragma unroll
        for (int na = 0; na < NA; na++)
            #pragma unroll
            for (int half = 0; half < 2; half++) {
                const int row = bm + wm + ma * 16 + g + half * 8;
                const int col = bn + wn + na * 8 + t * 2;
                float v0 = acc[ma][na][half * 2 + 0];
                float v1 = acc[ma][na][half * 2 + 1];

                const int which = col >> 10;
                const int c     = col & 1023;
                const int h     = c >> 6;
                const int d0    = c & 63;
                const int b8    = row >> 10;
                const int n     = row & 1023;
                const int bh    = b8 * H_ + h;
                if (which == 0) {
                    __half h0, l0, h1, l1;
                    splith(v0 * 0.125f, h0, l0); splith(v1 * 0.125f, h1, l1);
                    const size_t base = ((size_t)bh * N_ + n) * D_ + d0;
                    *(__half2*)(g_qh + base) = __halves2half2(h0, h1);
                    *(__half2*)(g_ql + base) = __halves2half2(l0, l1);
                } else if (which == 1) {
                    const size_t base = ((size_t)bh * N_ + n) * D_ + d0;
                    *(__half2*)(g_kh + base) =
                        __halves2half2(__float2half(v0), __float2half(v1));
                } else {
                    const size_t vb = (size_t)bh * D_ * N_ + n;
                    g_vTh[vb + (size_t)d0 * N_]       = __float2half(v0);
                    g_vTh[vb + (size_t)(d0 + 1) * N_] = __float2half(v1);
                }
            }
}

// ---------------------------------------------------------------------------
// Fused S = (qh+ql) @ kh^T -> softmax -> attn fp32 (2-term; K ring hi only).
// ---------------------------------------------------------------------------
#define Q_OFF  0
#define QL_OFF 4608
#define K_OFF  9216
#define KSTG   18432
#define S_OFF  46080
#define S_PIT  4144
#define SS_SMEM (S_OFF + 32 * S_PIT)   // 178688

__global__ void __launch_bounds__(256, 1) sscore_kernel(float* __restrict__ attn)
{
    extern __shared__ char smem[];
    const u32 sb   = smem_u32(smem);
    const int tid  = threadIdx.x;
    const int wid  = tid >> 5, lane = tid & 31;
    const int g    = lane >> 2, t = lane & 3;

    const int bh   = blockIdx.x >> 5;
    const int row0 = (blockIdx.x & 31) * 32;
    const int wm   = (wid & 1) * 16;
    const int wn   = (wid >> 1) * 32;

    const __half* Qh = g_qh + ((size_t)bh * N_ + row0) * D_;
    const __half* Ql = g_ql + ((size_t)bh * N_ + row0) * D_;
    const __half* Kh = g_kh + (size_t)bh * N_ * D_;

    {
        int r = tid >> 3, sgm = tid & 7;
        u32 off = (u32)(r * 144 + sgm * 16);
        *(float4*)(smem + Q_OFF + off)  = *(const float4*)(Qh + r * D_ + sgm * 8);
        *(float4*)(smem + QL_OFF + off) = *(const float4*)(Ql + r * D_ + sgm * 8);
    }

    auto issueK = [&](int c, int s) {
        const u32 base = sb + K_OFF + s * KSTG;
        const size_t ko = (size_t)c * 128 * D_;
        #pragma unroll
        for (int i = tid; i < 128 * 8; i += 256) {
            int r = i >> 3, sgm = i & 7;
            CP16(base + (u32)(r * 144 + sgm * 16), Kh + ko + r * D_ + sgm * 8);
        }
        CP_COMMIT();
    };

    const u32 arow = (u32)((wm + (lane & 15)) * 144 + ((lane >> 4) << 4));
    const u32 brow = (u32)((wn + (lane & 7) + ((lane >> 4) << 3)) * 144 + (((lane >> 3) & 1) << 4));

    issueK(0, 0);
    issueK(1, 1);
    for (int c = 0; c < 8; c++) {
        if (c < 7) CP_WAIT(1); else CP_WAIT(0);
        __syncthreads();

        const u32 kb0 = sb + K_OFF + (c & 1) * KSTG;
        float acc[4][4];
        #pragma unroll
        for (int j = 0; j < 4; j++)
            #pragma unroll
            for (int r = 0; r < 4; r++) acc[j][r] = 0.0f;

        #pragma unroll
        for (int ks = 0; ks < 4; ks++) {
            const u32 kb = ks * 32;
            u32 a_hi[4], a_lo[4], b_hi[4][2];
            u32 ad = sb + Q_OFF + arow + kb;
            ldm4(a_hi[0], a_hi[1], a_hi[2], a_hi[3], ad);
            ldm4(a_lo[0], a_lo[1], a_lo[2], a_lo[3], ad + QL_OFF);
            #pragma unroll
            for (int p = 0; p < 2; p++) {
                u32 bd = kb0 + brow + p * 16 * 144 + kb;
                ldm4(b_hi[2*p][0], b_hi[2*p][1], b_hi[2*p+1][0], b_hi[2*p+1][1], bd);
            }
            #pragma unroll
            for (int na = 0; na < 4; na++) {
                mma16816(acc[na], a_hi, b_hi[na]);
                mma16816(acc[na], a_lo, b_hi[na]);
            }
        }

        #pragma unroll
        for (int na = 0; na < 4; na++)
            #pragma unroll
            for (int half = 0; half < 2; half++) {
                int row = wm + g + half * 8;
                int col = c * 128 + wn + na * 8 + t * 2;
                *(float2*)(smem + S_OFF + row * S_PIT + col * 4) =
                    make_float2(acc[na][half * 2], acc[na][half * 2 + 1]);
            }

        __syncthreads();
        if (c + 2 < 8) issueK(c + 2, c & 1);
    }

    #pragma unroll
    for (int rr = 0; rr < 4; rr++) {
        const int r = wid * 4 + rr;
        const float* Srow = (const float*)(smem + S_OFF + r * S_PIT);
        float4 f[8];
        float m = -1e30f;
        #pragma unroll
        for (int i = 0; i < 8; i++) {
            f[i] = *(const float4*)(Srow + (lane + i * 32) * 4);
            m = fmaxf(m, fmaxf(fmaxf(f[i].x, f[i].y), fmaxf(f[i].z, f[i].w)));
        }
        #pragma unroll
        for (int o = 16; o > 0; o >>= 1) m = fmaxf(m, __shfl_xor_sync(0xffffffffu, m, o));
        float s = 0.0f;
        #pragma unroll
        for (int i = 0; i < 8; i++) {
            f[i].x = __expf(f[i].x - m); f[i].y = __expf(f[i].y - m);
            f[i].z = __expf(f[i].z - m); f[i].w = __expf(f[i].w - m);
            s += f[i].x + f[i].y + f[i].z + f[i].w;
        }
        #pragma unroll
        for (int o = 16; o > 0; o >>= 1) s += __shfl_xor_sync(0xffffffffu, s, o);
        const float inv = 1.0f / s;

        float* ap = attn + ((size_t)bh * N_ + row0 + r) * N_;
        #pragma unroll
        for (int i = 0; i < 8; i++) {
            *(float4*)(ap + (lane + i * 32) * 4) =
                make_float4(f[i].x * inv, f[i].y * inv, f[i].z * inv, f[i].w * inv);
        }
    }
}

// ---------------------------------------------------------------------------
// AV GEMM: ctx = (Ph+Pl) @ Vh (2-term; V ring hi only). P split in smem.
// ---------------------------------------------------------------------------
#define AV_ASTG   18432
#define AV_AH_OFF (3 * AV_ASTG)                    // 55296
#define AV_APART  10240
#define AV_B_OFF  (AV_AH_OFF + 2 * AV_APART)       // 75776
#define AV_BSTG   5120
#define AV_SMEM   (AV_B_OFF + 3 * AV_BSTG)         // 91136

__global__ void __launch_bounds__(256, 1) av_gemm(const float* __restrict__ attn)
{
    extern __shared__ char smem[];
    const u32 sb   = smem_u32(smem);
    const int tid  = threadIdx.x;
    const int wid  = tid >> 5, lane = tid & 31;
    const int g    = lane >> 2, t = lane & 3;

    const int bm = blockIdx.y * 128;
    const int z  = blockIdx.z;
    const int b8 = z >> 4, h = z & 15;
    const int wm = (wid & 3) * 32;
    const int wn = (wid >> 2) * 32;

    const float* Ap = attn + (size_t)z * N_ * N_ + (size_t)bm * N_;
    const __half* Vh = g_vTh + (size_t)z * D_ * N_;

    float acc[2][4][4];
    #pragma unroll
    for (int i = 0; i < 2; i++)
        #pragma unroll
        for (int j = 0; j < 4; j++)
            #pragma unroll
            for (int r = 0; r < 4; r++) acc[i][j][r] = 0.0f;

    auto issue_loads = [&](int ck, int s) {
        const int kofs = ck * 32;
        const u32 abase = sb + s * AV_ASTG;
        #pragma unroll
        for (int i = tid; i < 128 * 8; i += 256) {
            int r = i >> 3, sgm = i & 7;
            CP16(abase + (u32)(r * 144 + sgm * 16), Ap + (size_t)r * N_ + kofs + sgm * 4);
        }
        const u32 bbase = sb + AV_B_OFF + s * AV_BSTG;
        #pragma unroll
        for (int i = tid; i < 64 * 4; i += 256) {
            int r = i >> 2, sgm = i & 3;
            CP16(bbase + (u32)(r * 80 + sgm * 16), Vh + (size_t)r * N_ + kofs + sgm * 8);
        }
        CP_COMMIT();
    };

    const u32 arow = (u32)((wm + (lane & 15)) * 80 + ((lane >> 4) << 4));
    const u32 brow = (u32)((wn + (lane & 7) + ((lane >> 4) << 3)) * 80 + (((lane >> 3) & 1) << 4));

    issue_loads(0, 0);
    issue_loads(1, 1);
    issue_loads(2, 2);
    for (int ck = 0; ck < 32; ck++) {
        const int s = ck % 3;
        if (ck <= 29) CP_WAIT(2);
        else if (ck == 30) CP_WAIT(1);
        else CP_WAIT(0);
        __syncthreads();

        // convert P fp32 stage s -> hi/lo fp16 (80B pitch)
        {
            const char* src = smem + s * AV_ASTG + (tid >> 1) * 144 + (tid & 1) * 64;
            float4 v0 = *(const float4*)(src);
            float4 v1 = *(const float4*)(src + 16);
            float4 v2 = *(const float4*)(src + 32);
            float4 v3 = *(const float4*)(src + 48);
            float fv[16] = { v0.x,v0.y,v0.z,v0.w, v1.x,v1.y,v1.z,v1.w,
                             v2.x,v2.y,v2.z,v2.w, v3.x,v3.y,v3.z,v3.w };
            u32 hw[8], lw[8];
            #pragma unroll
            for (int p = 0; p < 8; p++) {
                __half h0, l0, h1, l1;
                splith(fv[2*p],   h0, l0);
                splith(fv[2*p+1], h1, l1);
                __half2 hh = __halves2half2(h0, h1), ll = __halves2half2(l0, l1);
                hw[p] = *(u32*)&hh; lw[p] = *(u32*)&ll;
            }
            char* dh = smem + AV_AH_OFF + (tid >> 1) * 80 + (tid & 1) * 32;
            char* dl = dh + AV_APART;
            *(uint4*)dh        = make_uint4(hw[0], hw[1], hw[2], hw[3]);
            *(uint4*)(dh + 16) = make_uint4(hw[4], hw[5], hw[6], hw[7]);
            *(uint4*)dl        = make_uint4(lw[0], lw[1], lw[2], lw[3]);
            *(uint4*)(dl + 16) = make_uint4(lw[4], lw[5], lw[6], lw[7]);
        }
        __syncthreads();

        {
            const u32 ah0 = sb + AV_AH_OFF;
            const u32 bb0 = sb + AV_B_OFF + s * AV_BSTG;
            #pragma unroll
            for (int ks = 0; ks < 2; ks++) {
                const u32 kb = ks * 32;
                u32 a_hi[2][4], a_lo[2][4], b_hi[4][2];
                #pragma unroll
                for (int ma = 0; ma < 2; ma++) {
                    u32 ad = ah0 + arow + ma * 16 * 80 + kb;
                    ldm4(a_hi[ma][0], a_hi[ma][1], a_hi[ma][2], a_hi[ma][3], ad);
                    ldm4(a_lo[ma][0], a_lo[ma][1], a_lo[ma][2], a_lo[ma][3], ad + AV_APART);
                }
                #pragma unroll
                for (int p = 0; p < 2; p++) {
                    u32 bd = bb0 + brow + p * 16 * 80 + kb;
                    ldm4(b_hi[2*p][0], b_hi[2*p][1], b_hi[2*p+1][0], b_hi[2*p+1][1], bd);
                }
                #pragma unroll
                for (int ma = 0; ma < 2; ma++)
                    #pragma unroll
                    for (int na = 0; na < 4; na++) {
                        mma16816(acc[ma][na], a_hi[ma], b_hi[na]);
                        mma16816(acc[ma][na], a_lo[ma], b_hi[na]);
                    }
            }
        }
        __syncthreads();
        if (ck + 3 < 32) issue_loads(ck + 3, s);
    }

    // epilogue: ctx split -> g_ch/g_cl
    #pragma unroll
    for (int ma = 0; ma < 2; ma++)
        #pragma unroll
        for (int na = 0; na < 4; na++)
            #pragma unroll
            for (int half = 0; half < 2; half++) {
                const int row = bm + wm + ma * 16 + g + half * 8;
                const int col = wn + na * 8 + t * 2;
                const size_t base = ((size_t)(b8 * N_ + row)) * C_ + h * 64 + col;
                __half h0, l0, h1, l1;
                splith(acc[ma][na][half * 2 + 0], h0, l0);
                splith(acc[ma][na][half * 2 + 1], h1, l1);
                *(__half2*)(g_ch + base) = __halves2half2(h0, h1);
                *(__half2*)(g_cl + base) = __halves2half2(l0, l1);
            }
}

// ---------------------------------------------------------------------------
// Projection GEMM: out = (ch+cl) @ wph + bias (2-term; w hi only).
// ---------------------------------------------------------------------------
#define PJ_PART  10240
#define PJ_STAGE (3 * PJ_PART)
#define PJ_SMEM  (3 * PJ_STAGE)   // 92160

__global__ void __launch_bounds__(256, 1) proj_gemm(float* __restrict__ out,
                                                    const float* __restrict__ bias)
{
    constexpr int NC = 32;
    constexpr int MA = 4;
    constexpr int NA = 4;

    extern __shared__ char smem[];
    const u32 sb   = smem_u32(smem);
    const int tid  = threadIdx.x;
    const int wid  = tid >> 5, lane = tid & 31;
    const int g    = lane >> 2, t = lane & 3;
    const int bn   = blockIdx.x * 128;
    const int bm   = blockIdx.y * 128;
    const int wm   = (wid & 1) * 64;
    const int wn   = (wid >> 1) * 32;

    const __half *Ah = g_ch + (size_t)bm * C_, *Al = g_cl + (size_t)bm * C_;
    const __half *Bh = g_wph + (size_t)bn * C_;

    float acc[MA][NA][4];
    #pragma unroll
    for (int i = 0; i < MA; i++)
        #pragma unroll
        for (int j = 0; j < NA; j++)
            #pragma unroll
            for (int r = 0; r < 4; r++) acc[i][j][r] = 0.0f;

    auto issue_loads = [&](int ck, int s) {
        const int kofs = ck * 32;
        const u32 base = sb + s * PJ_STAGE;
        #pragma unroll
        for (int i = tid; i < 128 * 4; i += 256) {
            int r = i >> 2, sgm = i & 3;
            u32 off = (u32)(r * 80 + sgm * 16);
            const size_t go = (size_t)r * C_ + kofs + sgm * 8;
            CP16(base + off,               Ah + go);
            CP16(base + PJ_PART + off,     Al + go);
            CP16(base + 2 * PJ_PART + off, Bh + go);
        }
        CP_COMMIT();
    };

    const u32 arow = (u32)((wm + (lane & 15)) * 80 + ((lane >> 4) << 4));
    const u32 brow = (u32)((wn + (lane & 7) + ((lane >> 4) << 3)) * 80 + (((lane >> 3) & 1) << 4));

    auto do_compute = [&](int s) {
        const u32 abase = sb + s * PJ_STAGE;
        const u32 bbase = abase + 2 * PJ_PART;
        #pragma unroll
        for (int ks = 0; ks < 2; ks++) {
            const u32 kb = ks * 32;
            u32 a_hi[MA][4], a_lo[MA][4], b_hi[NA][2];
            #pragma unroll
            for (int ma = 0; ma < MA; ma++) {
                u32 ad = abase + arow + ma * 16 * 80 + kb;
                ldm4(a_hi[ma][0], a_hi[ma][1], a_hi[ma][2], a_hi[ma][3], ad);
                ldm4(a_lo[ma][0], a_lo[ma][1], a_lo[ma][2], a_lo[ma][3], ad + PJ_PART);
            }
            #pragma unroll
            for (int p = 0; p < NA / 2; p++) {
                u32 bd = bbase + brow + p * 16 * 80 + kb;
                ldm4(b_hi[2*p][0], b_hi[2*p][1], b_hi[2*p+1][0], b_hi[2*p+1][1], bd);
            }
            #pragma unroll
            for (int ma = 0; ma < MA; ma++)
                #pragma unroll
                for (int na = 0; na < NA; na++) {
                    mma16816(acc[ma][na], a_hi[ma], b_hi[na]);
                    mma16816(acc[ma][na], a_lo[ma], b_hi[na]);
                }
        }
    };

    issue_loads(0, 0);
    issue_loads(1, 1);
    for (int ck = 0; ck < NC; ck++) {
        const int s = ck % 3;
        if (ck + 2 < NC) { issue_loads(ck + 2, (ck + 2) % 3); CP_WAIT(2); }
        else if (ck + 1 < NC) { CP_WAIT(1); }
        else { CP_WAIT(0); }
        __syncthreads();
        do_compute(s);
        __syncthreads();
    }

    #pragma unroll
    for (int ma = 0; ma < MA; ma++)
        #pragma unroll
        for (int na = 0; na < NA; na++)
            #pragma unroll
            for (int half = 0; half < 2; half++) {
                const int row = bm + wm + ma * 16 + g + half * 8;
                const int col = bn + wn + na * 8 + t * 2;
                float* dst = out + (size_t)row * C_ + col;
                *(float2*)dst = make_float2(acc[ma][na][half * 2 + 0] + bias[col],
                                            acc[ma][na][half * 2 + 1] + bias[col + 1]);
            }
}

// ---------------- conversion kernels ----------------
__global__ void __launch_bounds__(256) conv_x(const float* __restrict__ s)
{
    int i = blockIdx.x * 256 + threadIdx.x;
    float4 v = ((const float4*)s)[i];
    __half h0, l0, h1, l1, h2, l2, h3, l3;
    splith(v.x, h0, l0); splith(v.y, h1, l1);
    splith(v.z, h2, l2); splith(v.w, h3, l3);
    __half2* hp = (__half2*)g_xh;
    __half2* lp = (__half2*)g_xl;
    hp[i * 2]     = __halves2half2(h0, h1);
    hp[i * 2 + 1] = __halves2half2(h2, h3);
    lp[i * 2]     = __halves2half2(l0, l1);
    lp[i * 2 + 1] = __halves2half2(l2, l3);
}

// weights: transpose + fp16 hi only.  W=0: w_qkv -> g_wqh, W=1: w_proj -> g_wph
template <int W>
__global__ void __launch_bounds__(256) conv_wT(const float* __restrict__ s)
{
    constexpr int Cc = (W == 0) ? QKVC : C_;
    __half* dh = (W == 0) ? g_wqh : g_wph;

    __shared__ float tbuf[32][33];
    const int tx = threadIdx.x & 31, ty = threadIdx.x >> 5;
    const int c0 = blockIdx.x * 32, r0 = blockIdx.y * 32;
    #pragma unroll
    for (int j = 0; j < 4; j++)
        tbuf[ty + j * 8][tx] = s[(size_t)(r0 + ty + j * 8) * Cc + c0 + tx];
    __syncthreads();
    #pragma unroll
    for (int j = 0; j < 4; j++) {
        int i = ty + j * 8;
        dh[(size_t)(c0 + i) * C_ + r0 + tx] = __float2half(tbuf[tx][i]);
    }
}

// ---------------------------------------------------------------------------
extern "C" void kernel_launch(void* const* d_in, const int* in_sizes, int n_in,
                              void* d_out, int out_size)
{
    const float* x      = (const float*)d_in[0];
    const float* w_qkv  = (const float*)d_in[1];
    const float* w_proj = (const float*)d_in[2];
    const float* b_proj = (const float*)d_in[3];
    float* out  = (float*)d_out;
    float* attn = out + (size_t)M_ * C_;

    cudaFuncSetAttribute(qkv_gemm,      cudaFuncAttributeMaxDynamicSharedMemorySize, QK_SMEM);
    cudaFuncSetAttribute(sscore_kernel, cudaFuncAttributeMaxDynamicSharedMemorySize, SS_SMEM);
    cudaFuncSetAttribute(av_gemm,       cudaFuncAttributeMaxDynamicSharedMemorySize, AV_SMEM);
    cudaFuncSetAttribute(proj_gemm,     cudaFuncAttributeMaxDynamicSharedMemorySize, PJ_SMEM);

    // 1) input conversions
    conv_x<<<M_ * C_ / 1024, 256>>>(x);
    conv_wT<0><<<dim3(QKVC / 32, C_ / 32), 256>>>(w_qkv);
    conv_wT<1><<<dim3(C_ / 32, C_ / 32), 256>>>(w_proj);

    // 2) QKV GEMM (2-term) -> q hi/lo (scaled), k hi, vT hi
    qkv_gemm<<<dim3(QKVC / 128, M_ / 128), 256, QK_SMEM>>>();

    // 3) S + softmax -> attn fp32 (2-term)
    sscore_kernel<<<BH_ * 32, 256, SS_SMEM>>>(attn);

    // 4) ctx = attn(fp32) @ Vh (2-term)
    av_gemm<<<dim3(1, N_ / 128, BH_), 256, AV_SMEM>>>(attn);

    // 5) out = ctx @ w_proj + bias (2-term)
    proj_gemm<<<dim3(C_ / 128, M_ / 128), 256, PJ_SMEM>>>(out, b_proj);
}

// round 11
// speedup vs baseline: 1.9180x; 1.1257x over previous
#include <cuda_runtime.h>
#include <cuda_fp16.h>

typedef unsigned int u32;

#define B_   8
#define N_   1024
#define C_   1024
#define H_   16
#define D_   64
#define M_   (B_ * N_)     // 8192
#define QKVC 3072
#define BH_  (B_ * H_)     // 128

// ---------------- allocation-free scratch (device globals, fp16) ----------
__device__ __align__(256) __half g_xh[(size_t)M_ * C_],  g_xl[(size_t)M_ * C_];
__device__ __align__(256) __half g_wqh[(size_t)QKVC * C_];
__device__ __align__(256) __half g_wph[(size_t)C_ * C_];
__device__ __align__(256) __half g_qh[(size_t)BH_ * N_ * D_], g_ql[(size_t)BH_ * N_ * D_];
__device__ __align__(256) __half g_kh[(size_t)BH_ * N_ * D_];
__device__ __align__(256) __half g_vTh[(size_t)BH_ * D_ * N_];
__device__ __align__(256) __half g_ch[(size_t)M_ * C_];

// ---------------- helpers ----------------
__device__ __forceinline__ u32 smem_u32(const void* p) {
    u32 a;
    asm("{ .reg .u64 t; cvta.to.shared.u64 t, %1; cvt.u32.u64 %0, t; }" : "=r"(a) : "l"(p));
    return a;
}
#define CP16(dst, src) \
    asm volatile("cp.async.cg.shared.global [%0], [%1], 16;" :: "r"(dst), "l"(src) : "memory")
#define CP_COMMIT() asm volatile("cp.async.commit_group;" ::: "memory")
#define CP_WAIT(n)  asm volatile("cp.async.wait_group %0;" :: "n"(n) : "memory")

__device__ __forceinline__ void ldm4(u32& r0, u32& r1, u32& r2, u32& r3, u32 a) {
    asm volatile("ldmatrix.sync.aligned.m8n8.x4.shared.b16 {%0,%1,%2,%3}, [%4];"
        : "=r"(r0), "=r"(r1), "=r"(r2), "=r"(r3) : "r"(a));
}
__device__ __forceinline__ void mma16816(float* c, const u32* a, const u32* b) {
    asm volatile(
        "mma.sync.aligned.m16n8k16.row.col.f32.f16.f16.f32 "
        "{%0,%1,%2,%3}, {%4,%5,%6,%7}, {%8,%9}, {%0,%1,%2,%3};"
        : "+f"(c[0]), "+f"(c[1]), "+f"(c[2]), "+f"(c[3])
        : "r"(a[0]), "r"(a[1]), "r"(a[2]), "r"(a[3]), "r"(b[0]), "r"(b[1]));
}
__device__ __forceinline__ void splith(float v, __half& h, __half& l) {
    h = __float2half(v);
    l = __float2half(v - __half2float(h));
}

// ---------------------------------------------------------------------------
// QKV GEMM: 2-term fp16 ((ah+al)*bh). 256 thr, MA4 NA4, 3-stage ring.
// Epilogue: q hi+lo (scaled), k hi only, vT hi only.
// ---------------------------------------------------------------------------
#define QK_PART  10240
#define QK_STAGE (3 * QK_PART)
#define QK_SMEM  (3 * QK_STAGE)   // 92160

__global__ void __launch_bounds__(256, 1) qkv_gemm()
{
    constexpr int NC = 32;
    constexpr int MA = 4;
    constexpr int NA = 4;

    extern __shared__ char smem[];
    const u32 sb   = smem_u32(smem);
    const int tid  = threadIdx.x;
    const int wid  = tid >> 5, lane = tid & 31;
    const int g    = lane >> 2, t = lane & 3;
    const int bn   = blockIdx.x * 128;
    const int bm   = blockIdx.y * 128;
    const int wm   = (wid & 1) * 64;
    const int wn   = (wid >> 1) * 32;

    const __half *Ah = g_xh + (size_t)bm * C_, *Al = g_xl + (size_t)bm * C_;
    const __half *Bh = g_wqh + (size_t)bn * C_;

    float acc[MA][NA][4];
    #pragma unroll
    for (int i = 0; i < MA; i++)
        #pragma unroll
        for (int j = 0; j < NA; j++)
            #pragma unroll
            for (int r = 0; r < 4; r++) acc[i][j][r] = 0.0f;

    auto issue_loads = [&](int ck, int s) {
        const int kofs = ck * 32;
        const u32 base = sb + s * QK_STAGE;
        #pragma unroll
        for (int i = tid; i < 128 * 4; i += 256) {
            int r = i >> 2, sgm = i & 3;
            u32 off = (u32)(r * 80 + sgm * 16);
            const size_t go = (size_t)r * C_ + kofs + sgm * 8;
            CP16(base + off,               Ah + go);
            CP16(base + QK_PART + off,     Al + go);
            CP16(base + 2 * QK_PART + off, Bh + go);
        }
        CP_COMMIT();
    };

    const u32 arow = (u32)((wm + (lane & 15)) * 80 + ((lane >> 4) << 4));
    const u32 brow = (u32)((wn + (lane & 7) + ((lane >> 4) << 3)) * 80 + (((lane >> 3) & 1) << 4));

    auto do_compute = [&](int s) {
        const u32 abase = sb + s * QK_STAGE;
        const u32 bbase = abase + 2 * QK_PART;
        #pragma unroll
        for (int ks = 0; ks < 2; ks++) {
            const u32 kb = ks * 32;
            u32 a_hi[MA][4], a_lo[MA][4], b_hi[NA][2];
            #pragma unroll
            for (int ma = 0; ma < MA; ma++) {
                u32 ad = abase + arow + ma * 16 * 80 + kb;
                ldm4(a_hi[ma][0], a_hi[ma][1], a_hi[ma][2], a_hi[ma][3], ad);
                ldm4(a_lo[ma][0], a_lo[ma][1], a_lo[ma][2], a_lo[ma][3], ad + QK_PART);
            }
            #pragma unroll
            for (int p = 0; p < NA / 2; p++) {
                u32 bd = bbase + brow + p * 16 * 80 + kb;
                ldm4(b_hi[2*p][0], b_hi[2*p][1], b_hi[2*p+1][0], b_hi[2*p+1][1], bd);
            }
            #pragma unroll
            for (int ma = 0; ma < MA; ma++)
                #pragma unroll
                for (int na = 0; na < NA; na++) {
                    mma16816(acc[ma][na], a_hi[ma], b_hi[na]);
                    mma16816(acc[ma][na], a_lo[ma], b_hi[na]);
                }
        }
    };

    issue_loads(0, 0);
    issue_loads(1, 1);
    for (int ck = 0; ck < NC; ck++) {
        const int s = ck % 3;
        if (ck + 2 < NC) { issue_loads(ck + 2, (ck + 2) % 3); CP_WAIT(2); }
        else if (ck + 1 < NC) { CP_WAIT(1); }
        else { CP_WAIT(0); }
        __syncthreads();
        do_compute(s);
        __syncthreads();
    }

    // ---- epilogue ----
    #pragma unroll
    for (int ma = 0; ma < MA; ma++)
        #pragma unroll
        for (int na = 0; na < NA; na++)
            #pragma unroll
            for (int half = 0; half < 2; half++) {
                const int row = bm + wm + ma * 16 + g + half * 8;
                const int col = bn + wn + na * 8 + t * 2;
                float v0 = acc[ma][na][half * 2 + 0];
                float v1 = acc[ma][na][half * 2 + 1];

                const int which = col >> 10;
                const int c     = col & 1023;
                const int h     = c >> 6;
                const int d0    = c & 63;
                const int b8    = row >> 10;
                const int n     = row & 1023;
                const int bh    = b8 * H_ + h;
                if (which == 0) {
                    __half h0, l0, h1, l1;
                    splith(v0 * 0.125f, h0, l0); splith(v1 * 0.125f, h1, l1);
                    const size_t base = ((size_t)bh * N_ + n) * D_ + d0;
                    *(__half2*)(g_qh + base) = __halves2half2(h0, h1);
                    *(__half2*)(g_ql + base) = __halves2half2(l0, l1);
                } else if (which == 1) {
                    const size_t base = ((size_t)bh * N_ + n) * D_ + d0;
                    *(__half2*)(g_kh + base) =
                        __halves2half2(__float2half(v0), __float2half(v1));
                } else {
                    const size_t vb = (size_t)bh * D_ * N_ + n;
                    g_vTh[vb + (size_t)d0 * N_]       = __float2half(v0);
                    g_vTh[vb + (size_t)(d0 + 1) * N_] = __float2half(v1);
                }
            }
}

// ---------------------------------------------------------------------------
// Fused S = (qh+ql) @ kh^T -> softmax -> attn fp32 (2-term, unchanged).
// ---------------------------------------------------------------------------
#define Q_OFF  0
#define QL_OFF 4608
#define K_OFF  9216
#define KSTG   18432
#define S_OFF  46080
#define S_PIT  4144
#define SS_SMEM (S_OFF + 32 * S_PIT)   // 178688

__global__ void __launch_bounds__(256, 1) sscore_kernel(float* __restrict__ attn)
{
    extern __shared__ char smem[];
    const u32 sb   = smem_u32(smem);
    const int tid  = threadIdx.x;
    const int wid  = tid >> 5, lane = tid & 31;
    const int g    = lane >> 2, t = lane & 3;

    const int bh   = blockIdx.x >> 5;
    const int row0 = (blockIdx.x & 31) * 32;
    const int wm   = (wid & 1) * 16;
    const int wn   = (wid >> 1) * 32;

    const __half* Qh = g_qh + ((size_t)bh * N_ + row0) * D_;
    const __half* Ql = g_ql + ((size_t)bh * N_ + row0) * D_;
    const __half* Kh = g_kh + (size_t)bh * N_ * D_;

    {
        int r = tid >> 3, sgm = tid & 7;
        u32 off = (u32)(r * 144 + sgm * 16);
        *(float4*)(smem + Q_OFF + off)  = *(const float4*)(Qh + r * D_ + sgm * 8);
        *(float4*)(smem + QL_OFF + off) = *(const float4*)(Ql + r * D_ + sgm * 8);
    }

    auto issueK = [&](int c, int s) {
        const u32 base = sb + K_OFF + s * KSTG;
        const size_t ko = (size_t)c * 128 * D_;
        #pragma unroll
        for (int i = tid; i < 128 * 8; i += 256) {
            int r = i >> 3, sgm = i & 7;
            CP16(base + (u32)(r * 144 + sgm * 16), Kh + ko + r * D_ + sgm * 8);
        }
        CP_COMMIT();
    };

    const u32 arow = (u32)((wm + (lane & 15)) * 144 + ((lane >> 4) << 4));
    const u32 brow = (u32)((wn + (lane & 7) + ((lane >> 4) << 3)) * 144 + (((lane >> 3) & 1) << 4));

    issueK(0, 0);
    issueK(1, 1);
    for (int c = 0; c < 8; c++) {
        if (c < 7) CP_WAIT(1); else CP_WAIT(0);
        __syncthreads();

        const u32 kb0 = sb + K_OFF + (c & 1) * KSTG;
        float acc[4][4];
        #pragma unroll
        for (int j = 0; j < 4; j++)
            #pragma unroll
            for (int r = 0; r < 4; r++) acc[j][r] = 0.0f;

        #pragma unroll
        for (int ks = 0; ks < 4; ks++) {
            const u32 kb = ks * 32;
            u32 a_hi[4], a_lo[4], b_hi[4][2];
            u32 ad = sb + Q_OFF + arow + kb;
            ldm4(a_hi[0], a_hi[1], a_hi[2], a_hi[3], ad);
            ldm4(a_lo[0], a_lo[1], a_lo[2], a_lo[3], ad + QL_OFF);
            #pragma unroll
            for (int p = 0; p < 2; p++) {
                u32 bd = kb0 + brow + p * 16 * 144 + kb;
                ldm4(b_hi[2*p][0], b_hi[2*p][1], b_hi[2*p+1][0], b_hi[2*p+1][1], bd);
            }
            #pragma unroll
            for (int na = 0; na < 4; na++) {
                mma16816(acc[na], a_hi, b_hi[na]);
                mma16816(acc[na], a_lo, b_hi[na]);
            }
        }

        #pragma unroll
        for (int na = 0; na < 4; na++)
            #pragma unroll
            for (int half = 0; half < 2; half++) {
                int row = wm + g + half * 8;
                int col = c * 128 + wn + na * 8 + t * 2;
                *(float2*)(smem + S_OFF + row * S_PIT + col * 4) =
                    make_float2(acc[na][half * 2], acc[na][half * 2 + 1]);
            }

        __syncthreads();
        if (c + 2 < 8) issueK(c + 2, c & 1);
    }

    #pragma unroll
    for (int rr = 0; rr < 4; rr++) {
        const int r = wid * 4 + rr;
        const float* Srow = (const float*)(smem + S_OFF + r * S_PIT);
        float4 f[8];
        float m = -1e30f;
        #pragma unroll
        for (int i = 0; i < 8; i++) {
            f[i] = *(const float4*)(Srow + (lane + i * 32) * 4);
            m = fmaxf(m, fmaxf(fmaxf(f[i].x, f[i].y), fmaxf(f[i].z, f[i].w)));
        }
        #pragma unroll
        for (int o = 16; o > 0; o >>= 1) m = fmaxf(m, __shfl_xor_sync(0xffffffffu, m, o));
        float s = 0.0f;
        #pragma unroll
        for (int i = 0; i < 8; i++) {
            f[i].x = __expf(f[i].x - m); f[i].y = __expf(f[i].y - m);
            f[i].z = __expf(f[i].z - m); f[i].w = __expf(f[i].w - m);
            s += f[i].x + f[i].y + f[i].z + f[i].w;
        }
        #pragma unroll
        for (int o = 16; o > 0; o >>= 1) s += __shfl_xor_sync(0xffffffffu, s, o);
        const float inv = 1.0f / s;

        float* ap = attn + ((size_t)bh * N_ + row0 + r) * N_;
        #pragma unroll
        for (int i = 0; i < 8; i++) {
            *(float4*)(ap + (lane + i * 32) * 4) =
                make_float4(f[i].x * inv, f[i].y * inv, f[i].z * inv, f[i].w * inv);
        }
    }
}

// ---------------------------------------------------------------------------
// AV GEMM: ctx = Ph @ Vh (1-term; P rounded to fp16 hi in smem).
// ---------------------------------------------------------------------------
#define AV_ASTG   18432
#define AV_AH_OFF (3 * AV_ASTG)                    // 55296
#define AV_B_OFF  (AV_AH_OFF + 10240)              // 65536
#define AV_BSTG   5120
#define AV_SMEM   (AV_B_OFF + 3 * AV_BSTG)         // 80896

__global__ void __launch_bounds__(256, 1) av_gemm(const float* __restrict__ attn)
{
    extern __shared__ char smem[];
    const u32 sb   = smem_u32(smem);
    const int tid  = threadIdx.x;
    const int wid  = tid >> 5, lane = tid & 31;
    const int g    = lane >> 2, t = lane & 3;

    const int bm = blockIdx.y * 128;
    const int z  = blockIdx.z;
    const int b8 = z >> 4, h = z & 15;
    const int wm = (wid & 3) * 32;
    const int wn = (wid >> 2) * 32;

    const float* Ap = attn + (size_t)z * N_ * N_ + (size_t)bm * N_;
    const __half* Vh = g_vTh + (size_t)z * D_ * N_;

    float acc[2][4][4];
    #pragma unroll
    for (int i = 0; i < 2; i++)
        #pragma unroll
        for (int j = 0; j < 4; j++)
            #pragma unroll
            for (int r = 0; r < 4; r++) acc[i][j][r] = 0.0f;

    auto issue_loads = [&](int ck, int s) {
        const int kofs = ck * 32;
        const u32 abase = sb + s * AV_ASTG;
        #pragma unroll
        for (int i = tid; i < 128 * 8; i += 256) {
            int r = i >> 3, sgm = i & 7;
            CP16(abase + (u32)(r * 144 + sgm * 16), Ap + (size_t)r * N_ + kofs + sgm * 4);
        }
        const u32 bbase = sb + AV_B_OFF + s * AV_BSTG;
        #pragma unroll
        for (int i = tid; i < 64 * 4; i += 256) {
            int r = i >> 2, sgm = i & 3;
            CP16(bbase + (u32)(r * 80 + sgm * 16), Vh + (size_t)r * N_ + kofs + sgm * 8);
        }
        CP_COMMIT();
    };

    const u32 arow = (u32)((wm + (lane & 15)) * 80 + ((lane >> 4) << 4));
    const u32 brow = (u32)((wn + (lane & 7) + ((lane >> 4) << 3)) * 80 + (((lane >> 3) & 1) << 4));

    issue_loads(0, 0);
    issue_loads(1, 1);
    issue_loads(2, 2);
    for (int ck = 0; ck < 32; ck++) {
        const int s = ck % 3;
        if (ck <= 29) CP_WAIT(2);
        else if (ck == 30) CP_WAIT(1);
        else CP_WAIT(0);
        __syncthreads();

        // convert P fp32 stage s -> fp16 hi (80B pitch)
        {
            const char* src = smem + s * AV_ASTG + (tid >> 1) * 144 + (tid & 1) * 64;
            float4 v0 = *(const float4*)(src);
            float4 v1 = *(const float4*)(src + 16);
            float4 v2 = *(const float4*)(src + 32);
            float4 v3 = *(const float4*)(src + 48);
            __half2 p0 = __halves2half2(__float2half(v0.x), __float2half(v0.y));
            __half2 p1 = __halves2half2(__float2half(v0.z), __float2half(v0.w));
            __half2 p2 = __halves2half2(__float2half(v1.x), __float2half(v1.y));
            __half2 p3 = __halves2half2(__float2half(v1.z), __float2half(v1.w));
            __half2 p4 = __halves2half2(__float2half(v2.x), __float2half(v2.y));
            __half2 p5 = __halves2half2(__float2half(v2.z), __float2half(v2.w));
            __half2 p6 = __halves2half2(__float2half(v3.x), __float2half(v3.y));
            __half2 p7 = __halves2half2(__float2half(v3.z), __float2half(v3.w));
            char* dh = smem + AV_AH_OFF + (tid >> 1) * 80 + (tid & 1) * 32;
            *(uint4*)dh        = make_uint4(*(u32*)&p0, *(u32*)&p1, *(u32*)&p2, *(u32*)&p3);
            *(uint4*)(dh + 16) = make_uint4(*(u32*)&p4, *(u32*)&p5, *(u32*)&p6, *(u32*)&p7);
        }
        __syncthreads();

        {
            const u32 ah0 = sb + AV_AH_OFF;
            const u32 bb0 = sb + AV_B_OFF + s * AV_BSTG;
            #pragma unroll
            for (int ks = 0; ks < 2; ks++) {
                const u32 kb = ks * 32;
                u32 a_hi[2][4], b_hi[4][2];
                #pragma unroll
                for (int ma = 0; ma < 2; ma++) {
                    u32 ad = ah0 + arow + ma * 16 * 80 + kb;
                    ldm4(a_hi[ma][0], a_hi[ma][1], a_hi[ma][2], a_hi[ma][3], ad);
                }
                #pragma unroll
                for (int p = 0; p < 2; p++) {
                    u32 bd = bb0 + brow + p * 16 * 80 + kb;
                    ldm4(b_hi[2*p][0], b_hi[2*p][1], b_hi[2*p+1][0], b_hi[2*p+1][1], bd);
                }
                #pragma unroll
                for (int ma = 0; ma < 2; ma++)
                    #pragma unroll
                    for (int na = 0; na < 4; na++)
                        mma16816(acc[ma][na], a_hi[ma], b_hi[na]);
            }
        }
        __syncthreads();
        if (ck + 3 < 32) issue_loads(ck + 3, s);
    }

    // epilogue: ctx hi only -> g_ch
    #pragma unroll
    for (int ma = 0; ma < 2; ma++)
        #pragma unroll
        for (int na = 0; na < 4; na++)
            #pragma unroll
            for (int half = 0; half < 2; half++) {
                const int row = bm + wm + ma * 16 + g + half * 8;
                const int col = wn + na * 8 + t * 2;
                const size_t base = ((size_t)(b8 * N_ + row)) * C_ + h * 64 + col;
                *(__half2*)(g_ch + base) =
                    __halves2half2(__float2half(acc[ma][na][half * 2 + 0]),
                                   __float2half(acc[ma][na][half * 2 + 1]));
            }
}

// ---------------------------------------------------------------------------
// Projection GEMM: out = ch @ wph + bias (1-term).
// ---------------------------------------------------------------------------
#define PJ_PART  10240
#define PJ_STAGE (2 * PJ_PART)
#define PJ_SMEM  (3 * PJ_STAGE)   // 61440

__global__ void __launch_bounds__(256, 1) proj_gemm(float* __restrict__ out,
                                                    const float* __restrict__ bias)
{
    constexpr int NC = 32;
    constexpr int MA = 4;
    constexpr int NA = 4;

    extern __shared__ char smem[];
    const u32 sb   = smem_u32(smem);
    const int tid  = threadIdx.x;
    const int wid  = tid >> 5, lane = tid & 31;
    const int g    = lane >> 2, t = lane & 3;
    const int bn   = blockIdx.x * 128;
    const int bm   = blockIdx.y * 128;
    const int wm   = (wid & 1) * 64;
    const int wn   = (wid >> 1) * 32;

    const __half *Ah = g_ch + (size_t)bm * C_;
    const __half *Bh = g_wph + (size_t)bn * C_;

    float acc[MA][NA][4];
    #pragma unroll
    for (int i = 0; i < MA; i++)
        #pragma unroll
        for (int j = 0; j < NA; j++)
            #pragma unroll
            for (int r = 0; r < 4; r++) acc[i][j][r] = 0.0f;

    auto issue_loads = [&](int ck, int s) {
        const int kofs = ck * 32;
        const u32 base = sb + s * PJ_STAGE;
        #pragma unroll
        for (int i = tid; i < 128 * 4; i += 256) {
            int r = i >> 2, sgm = i & 3;
            u32 off = (u32)(r * 80 + sgm * 16);
            const size_t go = (size_t)r * C_ + kofs + sgm * 8;
            CP16(base + off,           Ah + go);
            CP16(base + PJ_PART + off, Bh + go);
        }
        CP_COMMIT();
    };

    const u32 arow = (u32)((wm + (lane & 15)) * 80 + ((lane >> 4) << 4));
    const u32 brow = (u32)((wn + (lane & 7) + ((lane >> 4) << 3)) * 80 + (((lane >> 3) & 1) << 4));

    auto do_compute = [&](int s) {
        const u32 abase = sb + s * PJ_STAGE;
        const u32 bbase = abase + PJ_PART;
        #pragma unroll
        for (int ks = 0; ks < 2; ks++) {
            const u32 kb = ks * 32;
            u32 a_hi[MA][4], b_hi[NA][2];
            #pragma unroll
            for (int ma = 0; ma < MA; ma++) {
                u32 ad = abase + arow + ma * 16 * 80 + kb;
                ldm4(a_hi[ma][0], a_hi[ma][1], a_hi[ma][2], a_hi[ma][3], ad);
            }
            #pragma unroll
            for (int p = 0; p < NA / 2; p++) {
                u32 bd = bbase + brow + p * 16 * 80 + kb;
                ldm4(b_hi[2*p][0], b_hi[2*p][1], b_hi[2*p+1][0], b_hi[2*p+1][1], bd);
            }
            #pragma unroll
            for (int ma = 0; ma < MA; ma++)
                #pragma unroll
                for (int na = 0; na < NA; na++)
                    mma16816(acc[ma][na], a_hi[ma], b_hi[na]);
        }
    };

    issue_loads(0, 0);
    issue_loads(1, 1);
    for (int ck = 0; ck < NC; ck++) {
        const int s = ck % 3;
        if (ck + 2 < NC) { issue_loads(ck + 2, (ck + 2) % 3); CP_WAIT(2); }
        else if (ck + 1 < NC) { CP_WAIT(1); }
        else { CP_WAIT(0); }
        __syncthreads();
        do_compute(s);
        __syncthreads();
    }

    #pragma unroll
    for (int ma = 0; ma < MA; ma++)
        #pragma unroll
        for (int na = 0; na < NA; na++)
            #pragma unroll
            for (int half = 0; half < 2; half++) {
                const int row = bm + wm + ma * 16 + g + half * 8;
                const int col = bn + wn + na * 8 + t * 2;
                float* dst = out + (size_t)row * C_ + col;
                *(float2*)dst = make_float2(acc[ma][na][half * 2 + 0] + bias[col],
                                            acc[ma][na][half * 2 + 1] + bias[col + 1]);
            }
}

// ---------------- conversion kernels ----------------
__global__ void __launch_bounds__(256) conv_x(const float* __restrict__ s)
{
    int i = blockIdx.x * 256 + threadIdx.x;
    float4 v = ((const float4*)s)[i];
    __half h0, l0, h1, l1, h2, l2, h3, l3;
    splith(v.x, h0, l0); splith(v.y, h1, l1);
    splith(v.z, h2, l2); splith(v.w, h3, l3);
    __half2* hp = (__half2*)g_xh;
    __half2* lp = (__half2*)g_xl;
    hp[i * 2]     = __halves2half2(h0, h1);
    hp[i * 2 + 1] = __halves2half2(h2, h3);
    lp[i * 2]     = __halves2half2(l0, l1);
    lp[i * 2 + 1] = __halves2half2(l2, l3);
}

// weights: transpose + fp16 hi only.  W=0: w_qkv -> g_wqh, W=1: w_proj -> g_wph
template <int W>
__global__ void __launch_bounds__(256) conv_wT(const float* __restrict__ s)
{
    constexpr int Cc = (W == 0) ? QKVC : C_;
    __half* dh = (W == 0) ? g_wqh : g_wph;

    __shared__ float tbuf[32][33];
    const int tx = threadIdx.x & 31, ty = threadIdx.x >> 5;
    const int c0 = blockIdx.x * 32, r0 = blockIdx.y * 32;
    #pragma unroll
    for (int j = 0; j < 4; j++)
        tbuf[ty + j * 8][tx] = s[(size_t)(r0 + ty + j * 8) * Cc + c0 + tx];
    __syncthreads();
    #pragma unroll
    for (int j = 0; j < 4; j++) {
        int i = ty + j * 8;
        dh[(size_t)(c0 + i) * C_ + r0 + tx] = __float2half(tbuf[tx][i]);
    }
}

// ---------------------------------------------------------------------------
extern "C" void kernel_launch(void* const* d_in, const int* in_sizes, int n_in,
                              void* d_out, int out_size)
{
    const float* x      = (const float*)d_in[0];
    const float* w_qkv  = (const float*)d_in[1];
    const float* w_proj = (const float*)d_in[2];
    const float* b_proj = (const float*)d_in[3];
    float* out  = (float*)d_out;
    float* attn = out + (size_t)M_ * C_;

    cudaFuncSetAttribute(qkv_gemm,      cudaFuncAttributeMaxDynamicSharedMemorySize, QK_SMEM);
    cudaFuncSetAttribute(sscore_kernel, cudaFuncAttributeMaxDynamicSharedMemorySize, SS_SMEM);
    cudaFuncSetAttribute(av_gemm,       cudaFuncAttributeMaxDynamicSharedMemorySize, AV_SMEM);
    cudaFuncSetAttribute(proj_gemm,     cudaFuncAttributeMaxDynamicSharedMemorySize, PJ_SMEM);

    // 1) input conversions
    conv_x<<<M_ * C_ / 1024, 256>>>(x);
    conv_wT<0><<<dim3(QKVC / 32, C_ / 32), 256>>>(w_qkv);
    conv_wT<1><<<dim3(C_ / 32, C_ / 32), 256>>>(w_proj);

    // 2) QKV GEMM (2-term) -> q hi/lo (scaled), k hi, vT hi
    qkv_gemm<<<dim3(QKVC / 128, M_ / 128), 256, QK_SMEM>>>();

    // 3) S + softmax -> attn fp32 (2-term)
    sscore_kernel<<<BH_ * 32, 256, SS_SMEM>>>(attn);

    // 4) ctx = attn(fp16-hi) @ Vh (1-term)
    av_gemm<<<dim3(1, N_ / 128, BH_), 256, AV_SMEM>>>(attn);

    // 5) out = ctx @ w_proj + bias (1-term)
    proj_gemm<<<dim3(C_ / 128, M_ / 128), 256, PJ_SMEM>>>(out, b_proj);
}

// round 12
// speedup vs baseline: 2.3408x; 1.2205x over previous
#include <cuda_runtime.h>
#include <cuda_fp16.h>

typedef unsigned int u32;

#define B_   8
#define N_   1024
#define C_   1024
#define H_   16
#define D_   64
#define M_   (B_ * N_)     // 8192
#define QKVC 3072
#define BH_  (B_ * H_)     // 128

// ---------------- allocation-free scratch (device globals, fp16) ----------
__device__ __align__(256) __half g_xh[(size_t)M_ * C_];
__device__ __align__(256) __half g_wqh[(size_t)QKVC * C_];
__device__ __align__(256) __half g_wph[(size_t)C_ * C_];
__device__ __align__(256) __half g_qh[(size_t)BH_ * N_ * D_];
__device__ __align__(256) __half g_kh[(size_t)BH_ * N_ * D_];
__device__ __align__(256) __half g_vTh[(size_t)BH_ * D_ * N_];
__device__ __align__(256) __half g_ch[(size_t)M_ * C_];

// ---------------- helpers ----------------
__device__ __forceinline__ u32 smem_u32(const void* p) {
    u32 a;
    asm("{ .reg .u64 t; cvta.to.shared.u64 t, %1; cvt.u32.u64 %0, t; }" : "=r"(a) : "l"(p));
    return a;
}
#define CP16(dst, src) \
    asm volatile("cp.async.cg.shared.global [%0], [%1], 16;" :: "r"(dst), "l"(src) : "memory")
#define CP_COMMIT() asm volatile("cp.async.commit_group;" ::: "memory")
#define CP_WAIT(n)  asm volatile("cp.async.wait_group %0;" :: "n"(n) : "memory")

__device__ __forceinline__ void ldm4(u32& r0, u32& r1, u32& r2, u32& r3, u32 a) {
    asm volatile("ldmatrix.sync.aligned.m8n8.x4.shared.b16 {%0,%1,%2,%3}, [%4];"
        : "=r"(r0), "=r"(r1), "=r"(r2), "=r"(r3) : "r"(a));
}
__device__ __forceinline__ void mma16816(float* c, const u32* a, const u32* b) {
    asm volatile(
        "mma.sync.aligned.m16n8k16.row.col.f32.f16.f16.f32 "
        "{%0,%1,%2,%3}, {%4,%5,%6,%7}, {%8,%9}, {%0,%1,%2,%3};"
        : "+f"(c[0]), "+f"(c[1]), "+f"(c[2]), "+f"(c[3])
        : "r"(a[0]), "r"(a[1]), "r"(a[2]), "r"(a[3]), "r"(b[0]), "r"(b[1]));
}

// ---------------------------------------------------------------------------
// QKV GEMM: 1-term fp16 (xh * wh). 256 thr, MA4 NA4, 3-stage cp.async ring.
// Epilogue: q (scaled), k, vT — all fp16.
// ---------------------------------------------------------------------------
#define QK_PART  10240
#define QK_STAGE (2 * QK_PART)
#define QK_SMEM  (3 * QK_STAGE)   // 61440

__global__ void __launch_bounds__(256, 1) qkv_gemm()
{
    constexpr int NC = 32;
    constexpr int MA = 4;
    constexpr int NA = 4;

    extern __shared__ char smem[];
    const u32 sb   = smem_u32(smem);
    const int tid  = threadIdx.x;
    const int wid  = tid >> 5, lane = tid & 31;
    const int g    = lane >> 2, t = lane & 3;
    const int bn   = blockIdx.x * 128;
    const int bm   = blockIdx.y * 128;
    const int wm   = (wid & 1) * 64;
    const int wn   = (wid >> 1) * 32;

    const __half *Ah = g_xh + (size_t)bm * C_;
    const __half *Bh = g_wqh + (size_t)bn * C_;

    float acc[MA][NA][4];
    #pragma unroll
    for (int i = 0; i < MA; i++)
        #pragma unroll
        for (int j = 0; j < NA; j++)
            #pragma unroll
            for (int r = 0; r < 4; r++) acc[i][j][r] = 0.0f;

    auto issue_loads = [&](int ck, int s) {
        const int kofs = ck * 32;
        const u32 base = sb + s * QK_STAGE;
        #pragma unroll
        for (int i = tid; i < 128 * 4; i += 256) {
            int r = i >> 2, sgm = i & 3;
            u32 off = (u32)(r * 80 + sgm * 16);
            const size_t go = (size_t)r * C_ + kofs + sgm * 8;
            CP16(base + off,           Ah + go);
            CP16(base + QK_PART + off, Bh + go);
        }
        CP_COMMIT();
    };

    const u32 arow = (u32)((wm + (lane & 15)) * 80 + ((lane >> 4) << 4));
    const u32 brow = (u32)((wn + (lane & 7) + ((lane >> 4) << 3)) * 80 + (((lane >> 3) & 1) << 4));

    auto do_compute = [&](int s) {
        const u32 abase = sb + s * QK_STAGE;
        const u32 bbase = abase + QK_PART;
        #pragma unroll
        for (int ks = 0; ks < 2; ks++) {
            const u32 kb = ks * 32;
            u32 a_hi[MA][4], b_hi[NA][2];
            #pragma unroll
            for (int ma = 0; ma < MA; ma++) {
                u32 ad = abase + arow + ma * 16 * 80 + kb;
                ldm4(a_hi[ma][0], a_hi[ma][1], a_hi[ma][2], a_hi[ma][3], ad);
            }
            #pragma unroll
            for (int p = 0; p < NA / 2; p++) {
                u32 bd = bbase + brow + p * 16 * 80 + kb;
                ldm4(b_hi[2*p][0], b_hi[2*p][1], b_hi[2*p+1][0], b_hi[2*p+1][1], bd);
            }
            #pragma unroll
            for (int ma = 0; ma < MA; ma++)
                #pragma unroll
                for (int na = 0; na < NA; na++)
                    mma16816(acc[ma][na], a_hi[ma], b_hi[na]);
        }
    };

    issue_loads(0, 0);
    issue_loads(1, 1);
    for (int ck = 0; ck < NC; ck++) {
        const int s = ck % 3;
        if (ck + 2 < NC) { issue_loads(ck + 2, (ck + 2) % 3); CP_WAIT(2); }
        else if (ck + 1 < NC) { CP_WAIT(1); }
        else { CP_WAIT(0); }
        __syncthreads();
        do_compute(s);
        __syncthreads();
    }

    // ---- epilogue ----
    #pragma unroll
    for (int ma = 0; ma < MA; ma++)
        #pragma unroll
        for (int na = 0; na < NA; na++)
            #pragma unroll
            for (int half = 0; half < 2; half++) {
                const int row = bm + wm + ma * 16 + g + half * 8;
                const int col = bn + wn + na * 8 + t * 2;
                float v0 = acc[ma][na][half * 2 + 0];
                float v1 = acc[ma][na][half * 2 + 1];

                const int which = col >> 10;
                const int c     = col & 1023;
                const int h     = c >> 6;
                const int d0    = c & 63;
                const int b8    = row >> 10;
                const int n     = row & 1023;
                const int bh    = b8 * H_ + h;
                if (which == 0) {
                    const size_t base = ((size_t)bh * N_ + n) * D_ + d0;
                    *(__half2*)(g_qh + base) =
                        __halves2half2(__float2half(v0 * 0.125f), __float2half(v1 * 0.125f));
                } else if (which == 1) {
                    const size_t base = ((size_t)bh * N_ + n) * D_ + d0;
                    *(__half2*)(g_kh + base) =
                        __halves2half2(__float2half(v0), __float2half(v1));
                } else {
                    const size_t vb = (size_t)bh * D_ * N_ + n;
                    g_vTh[vb + (size_t)d0 * N_]       = __float2half(v0);
                    g_vTh[vb + (size_t)(d0 + 1) * N_] = __float2half(v1);
                }
            }
}

// ---------------------------------------------------------------------------
// Fused S = qh @ kh^T -> softmax -> attn fp32 (1-term fp16).
// ---------------------------------------------------------------------------
#define Q_OFF  0
#define K_OFF  4608
#define KSTG   18432
#define S_OFF  41472
#define S_PIT  4144
#define SS_SMEM (S_OFF + 32 * S_PIT)   // 174080

__global__ void __launch_bounds__(256, 1) sscore_kernel(float* __restrict__ attn)
{
    extern __shared__ char smem[];
    const u32 sb   = smem_u32(smem);
    const int tid  = threadIdx.x;
    const int wid  = tid >> 5, lane = tid & 31;
    const int g    = lane >> 2, t = lane & 3;

    const int bh   = blockIdx.x >> 5;
    const int row0 = (blockIdx.x & 31) * 32;
    const int wm   = (wid & 1) * 16;
    const int wn   = (wid >> 1) * 32;

    const __half* Qh = g_qh + ((size_t)bh * N_ + row0) * D_;
    const __half* Kh = g_kh + (size_t)bh * N_ * D_;

    {
        int r = tid >> 3, sgm = tid & 7;
        u32 off = (u32)(r * 144 + sgm * 16);
        *(float4*)(smem + Q_OFF + off) = *(const float4*)(Qh + r * D_ + sgm * 8);
    }

    auto issueK = [&](int c, int s) {
        const u32 base = sb + K_OFF + s * KSTG;
        const size_t ko = (size_t)c * 128 * D_;
        #pragma unroll
        for (int i = tid; i < 128 * 8; i += 256) {
            int r = i >> 3, sgm = i & 7;
            CP16(base + (u32)(r * 144 + sgm * 16), Kh + ko + r * D_ + sgm * 8);
        }
        CP_COMMIT();
    };

    const u32 arow = (u32)((wm + (lane & 15)) * 144 + ((lane >> 4) << 4));
    const u32 brow = (u32)((wn + (lane & 7) + ((lane >> 4) << 3)) * 144 + (((lane >> 3) & 1) << 4));

    issueK(0, 0);
    issueK(1, 1);
    for (int c = 0; c < 8; c++) {
        if (c < 7) CP_WAIT(1); else CP_WAIT(0);
        __syncthreads();

        const u32 kb0 = sb + K_OFF + (c & 1) * KSTG;
        float acc[4][4];
        #pragma unroll
        for (int j = 0; j < 4; j++)
            #pragma unroll
            for (int r = 0; r < 4; r++) acc[j][r] = 0.0f;

        #pragma unroll
        for (int ks = 0; ks < 4; ks++) {
            const u32 kb = ks * 32;
            u32 a_hi[4], b_hi[4][2];
            u32 ad = sb + Q_OFF + arow + kb;
            ldm4(a_hi[0], a_hi[1], a_hi[2], a_hi[3], ad);
            #pragma unroll
            for (int p = 0; p < 2; p++) {
                u32 bd = kb0 + brow + p * 16 * 144 + kb;
                ldm4(b_hi[2*p][0], b_hi[2*p][1], b_hi[2*p+1][0], b_hi[2*p+1][1], bd);
            }
            #pragma unroll
            for (int na = 0; na < 4; na++)
                mma16816(acc[na], a_hi, b_hi[na]);
        }

        #pragma unroll
        for (int na = 0; na < 4; na++)
            #pragma unroll
            for (int half = 0; half < 2; half++) {
                int row = wm + g + half * 8;
                int col = c * 128 + wn + na * 8 + t * 2;
                *(float2*)(smem + S_OFF + row * S_PIT + col * 4) =
                    make_float2(acc[na][half * 2], acc[na][half * 2 + 1]);
            }

        __syncthreads();
        if (c + 2 < 8) issueK(c + 2, c & 1);
    }

    #pragma unroll
    for (int rr = 0; rr < 4; rr++) {
        const int r = wid * 4 + rr;
        const float* Srow = (const float*)(smem + S_OFF + r * S_PIT);
        float4 f[8];
        float m = -1e30f;
        #pragma unroll
        for (int i = 0; i < 8; i++) {
            f[i] = *(const float4*)(Srow + (lane + i * 32) * 4);
            m = fmaxf(m, fmaxf(fmaxf(f[i].x, f[i].y), fmaxf(f[i].z, f[i].w)));
        }
        #pragma unroll
        for (int o = 16; o > 0; o >>= 1) m = fmaxf(m, __shfl_xor_sync(0xffffffffu, m, o));
        float s = 0.0f;
        #pragma unroll
        for (int i = 0; i < 8; i++) {
            f[i].x = __expf(f[i].x - m); f[i].y = __expf(f[i].y - m);
            f[i].z = __expf(f[i].z - m); f[i].w = __expf(f[i].w - m);
            s += f[i].x + f[i].y + f[i].z + f[i].w;
        }
        #pragma unroll
        for (int o = 16; o > 0; o >>= 1) s += __shfl_xor_sync(0xffffffffu, s, o);
        const float inv = 1.0f / s;

        float* ap = attn + ((size_t)bh * N_ + row0 + r) * N_;
        #pragma unroll
        for (int i = 0; i < 8; i++) {
            *(float4*)(ap + (lane + i * 32) * 4) =
                make_float4(f[i].x * inv, f[i].y * inv, f[i].z * inv, f[i].w * inv);
        }
    }
}

// ---------------------------------------------------------------------------
// AV GEMM: ctx = Ph @ Vh (1-term; P rounded to fp16 in smem). Unchanged r11.
// ---------------------------------------------------------------------------
#define AV_ASTG   18432
#define AV_AH_OFF (3 * AV_ASTG)                    // 55296
#define AV_B_OFF  (AV_AH_OFF + 10240)              // 65536
#define AV_BSTG   5120
#define AV_SMEM   (AV_B_OFF + 3 * AV_BSTG)         // 80896

__global__ void __launch_bounds__(256, 1) av_gemm(const float* __restrict__ attn)
{
    extern __shared__ char smem[];
    const u32 sb   = smem_u32(smem);
    const int tid  = threadIdx.x;
    const int wid  = tid >> 5, lane = tid & 31;
    const int g    = lane >> 2, t = lane & 3;

    const int bm = blockIdx.y * 128;
    const int z  = blockIdx.z;
    const int b8 = z >> 4, h = z & 15;
    const int wm = (wid & 3) * 32;
    const int wn = (wid >> 2) * 32;

    const float* Ap = attn + (size_t)z * N_ * N_ + (size_t)bm * N_;
    const __half* Vh = g_vTh + (size_t)z * D_ * N_;

    float acc[2][4][4];
    #pragma unroll
    for (int i = 0; i < 2; i++)
        #pragma unroll
        for (int j = 0; j < 4; j++)
            #pragma unroll
            for (int r = 0; r < 4; r++) acc[i][j][r] = 0.0f;

    auto issue_loads = [&](int ck, int s) {
        const int kofs = ck * 32;
        const u32 abase = sb + s * AV_ASTG;
        #pragma unroll
        for (int i = tid; i < 128 * 8; i += 256) {
            int r = i >> 3, sgm = i & 7;
            CP16(abase + (u32)(r * 144 + sgm * 16), Ap + (size_t)r * N_ + kofs + sgm * 4);
        }
        const u32 bbase = sb + AV_B_OFF + s * AV_BSTG;
        #pragma unroll
        for (int i = tid; i < 64 * 4; i += 256) {
            int r = i >> 2, sgm = i & 3;
            CP16(bbase + (u32)(r * 80 + sgm * 16), Vh + (size_t)r * N_ + kofs + sgm * 8);
        }
        CP_COMMIT();
    };

    const u32 arow = (u32)((wm + (lane & 15)) * 80 + ((lane >> 4) << 4));
    const u32 brow = (u32)((wn + (lane & 7) + ((lane >> 4) << 3)) * 80 + (((lane >> 3) & 1) << 4));

    issue_loads(0, 0);
    issue_loads(1, 1);
    issue_loads(2, 2);
    for (int ck = 0; ck < 32; ck++) {
        const int s = ck % 3;
        if (ck <= 29) CP_WAIT(2);
        else if (ck == 30) CP_WAIT(1);
        else CP_WAIT(0);
        __syncthreads();

        {
            const char* src = smem + s * AV_ASTG + (tid >> 1) * 144 + (tid & 1) * 64;
            float4 v0 = *(const float4*)(src);
            float4 v1 = *(const float4*)(src + 16);
            float4 v2 = *(const float4*)(src + 32);
            float4 v3 = *(const float4*)(src + 48);
            __half2 p0 = __halves2half2(__float2half(v0.x), __float2half(v0.y));
            __half2 p1 = __halves2half2(__float2half(v0.z), __float2half(v0.w));
            __half2 p2 = __halves2half2(__float2half(v1.x), __float2half(v1.y));
            __half2 p3 = __halves2half2(__float2half(v1.z), __float2half(v1.w));
            __half2 p4 = __halves2half2(__float2half(v2.x), __float2half(v2.y));
            __half2 p5 = __halves2half2(__float2half(v2.z), __float2half(v2.w));
            __half2 p6 = __halves2half2(__float2half(v3.x), __float2half(v3.y));
            __half2 p7 = __halves2half2(__float2half(v3.z), __float2half(v3.w));
            char* dh = smem + AV_AH_OFF + (tid >> 1) * 80 + (tid & 1) * 32;
            *(uint4*)dh        = make_uint4(*(u32*)&p0, *(u32*)&p1, *(u32*)&p2, *(u32*)&p3);
            *(uint4*)(dh + 16) = make_uint4(*(u32*)&p4, *(u32*)&p5, *(u32*)&p6, *(u32*)&p7);
        }
        __syncthreads();

        {
            const u32 ah0 = sb + AV_AH_OFF;
            const u32 bb0 = sb + AV_B_OFF + s * AV_BSTG;
            #pragma unroll
            for (int ks = 0; ks < 2; ks++) {
                const u32 kb = ks * 32;
                u32 a_hi[2][4], b_hi[4][2];
                #pragma unroll
                for (int ma = 0; ma < 2; ma++) {
                    u32 ad = ah0 + arow + ma * 16 * 80 + kb;
                    ldm4(a_hi[ma][0], a_hi[ma][1], a_hi[ma][2], a_hi[ma][3], ad);
                }
                #pragma unroll
                for (int p = 0; p < 2; p++) {
                    u32 bd = bb0 + brow + p * 16 * 80 + kb;
                    ldm4(b_hi[2*p][0], b_hi[2*p][1], b_hi[2*p+1][0], b_hi[2*p+1][1], bd);
                }
                #pragma unroll
                for (int ma = 0; ma < 2; ma++)
                    #pragma unroll
                    for (int na = 0; na < 4; na++)
                        mma16816(acc[ma][na], a_hi[ma], b_hi[na]);
            }
        }
        __syncthreads();
        if (ck + 3 < 32) issue_loads(ck + 3, s);
    }

    #pragma unroll
    for (int ma = 0; ma < 2; ma++)
        #pragma unroll
        for (int na = 0; na < 4; na++)
            #pragma unroll
            for (int half = 0; half < 2; half++) {
                const int row = bm + wm + ma * 16 + g + half * 8;
                const int col = wn + na * 8 + t * 2;
                const size_t base = ((size_t)(b8 * N_ + row)) * C_ + h * 64 + col;
                *(__half2*)(g_ch + base) =
                    __halves2half2(__float2half(acc[ma][na][half * 2 + 0]),
                                   __float2half(acc[ma][na][half * 2 + 1]));
            }
}

// ---------------------------------------------------------------------------
// Projection GEMM: out = ch @ wph + bias (1-term). Unchanged r11.
// ---------------------------------------------------------------------------
#define PJ_PART  10240
#define PJ_STAGE (2 * PJ_PART)
#define PJ_SMEM  (3 * PJ_STAGE)   // 61440

__global__ void __launch_bounds__(256, 1) proj_gemm(float* __restrict__ out,
                                                    const float* __restrict__ bias)
{
    constexpr int NC = 32;
    constexpr int MA = 4;
    constexpr int NA = 4;

    extern __shared__ char smem[];
    const u32 sb   = smem_u32(smem);
    const int tid  = threadIdx.x;
    const int wid  = tid >> 5, lane = tid & 31;
    const int g    = lane >> 2, t = lane & 3;
    const int bn   = blockIdx.x * 128;
    const int bm   = blockIdx.y * 128;
    const int wm   = (wid & 1) * 64;
    const int wn   = (wid >> 1) * 32;

    const __half *Ah = g_ch + (size_t)bm * C_;
    const __half *Bh = g_wph + (size_t)bn * C_;

    float acc[MA][NA][4];
    #pragma unroll
    for (int i = 0; i < MA; i++)
        #pragma unroll
        for (int j = 0; j < NA; j++)
            #pragma unroll
            for (int r = 0; r < 4; r++) acc[i][j][r] = 0.0f;

    auto issue_loads = [&](int ck, int s) {
        const int kofs = ck * 32;
        const u32 base = sb + s * PJ_STAGE;
        #pragma unroll
        for (int i = tid; i < 128 * 4; i += 256) {
            int r = i >> 2, sgm = i & 3;
            u32 off = (u32)(r * 80 + sgm * 16);
            const size_t go = (size_t)r * C_ + kofs + sgm * 8;
            CP16(base + off,           Ah + go);
            CP16(base + PJ_PART + off, Bh + go);
        }
        CP_COMMIT();
    };

    const u32 arow = (u32)((wm + (lane & 15)) * 80 + ((lane >> 4) << 4));
    const u32 brow = (u32)((wn + (lane & 7) + ((lane >> 4) << 3)) * 80 + (((lane >> 3) & 1) << 4));

    auto do_compute = [&](int s) {
        const u32 abase = sb + s * PJ_STAGE;
        const u32 bbase = abase + PJ_PART;
        #pragma unroll
        for (int ks = 0; ks < 2; ks++) {
            const u32 kb = ks * 32;
            u32 a_hi[MA][4], b_hi[NA][2];
            #pragma unroll
            for (int ma = 0; ma < MA; ma++) {
                u32 ad = abase + arow + ma * 16 * 80 + kb;
                ldm4(a_hi[ma][0], a_hi[ma][1], a_hi[ma][2], a_hi[ma][3], ad);
            }
            #pragma unroll
            for (int p = 0; p < NA / 2; p++) {
                u32 bd = bbase + brow + p * 16 * 80 + kb;
                ldm4(b_hi[2*p][0], b_hi[2*p][1], b_hi[2*p+1][0], b_hi[2*p+1][1], bd);
            }
            #pragma unroll
            for (int ma = 0; ma < MA; ma++)
                #pragma unroll
                for (int na = 0; na < NA; na++)
                    mma16816(acc[ma][na], a_hi[ma], b_hi[na]);
        }
    };

    issue_loads(0, 0);
    issue_loads(1, 1);
    for (int ck = 0; ck < NC; ck++) {
        const int s = ck % 3;
        if (ck + 2 < NC) { issue_loads(ck + 2, (ck + 2) % 3); CP_WAIT(2); }
        else if (ck + 1 < NC) { CP_WAIT(1); }
        else { CP_WAIT(0); }
        __syncthreads();
        do_compute(s);
        __syncthreads();
    }

    #pragma unroll
    for (int ma = 0; ma < MA; ma++)
        #pragma unroll
        for (int na = 0; na < NA; na++)
            #pragma unroll
            for (int half = 0; half < 2; half++) {
                const int row = bm + wm + ma * 16 + g + half * 8;
                const int col = bn + wn + na * 8 + t * 2;
                float* dst = out + (size_t)row * C_ + col;
                *(float2*)dst = make_float2(acc[ma][na][half * 2 + 0] + bias[col],
                                            acc[ma][na][half * 2 + 1] + bias[col + 1]);
            }
}

// ---------------- conversion kernels ----------------
__global__ void __launch_bounds__(256) conv_x(const float* __restrict__ s)
{
    int i = blockIdx.x * 256 + threadIdx.x;
    float4 v = ((const float4*)s)[i];
    __half2* hp = (__half2*)g_xh;
    hp[i * 2]     = __halves2half2(__float2half(v.x), __float2half(v.y));
    hp[i * 2 + 1] = __halves2half2(__float2half(v.z), __float2half(v.w));
}

// weights: transpose + fp16.  W=0: w_qkv -> g_wqh, W=1: w_proj -> g_wph
template <int W>
__global__ void __launch_bounds__(256) conv_wT(const float* __restrict__ s)
{
    constexpr int Cc = (W == 0) ? QKVC : C_;
    __half* dh = (W == 0) ? g_wqh : g_wph;

    __shared__ float tbuf[32][33];
    const int tx = threadIdx.x & 31, ty = threadIdx.x >> 5;
    const int c0 = blockIdx.x * 32, r0 = blockIdx.y * 32;
    #pragma unroll
    for (int j = 0; j < 4; j++)
        tbuf[ty + j * 8][tx] = s[(size_t)(r0 + ty + j * 8) * Cc + c0 + tx];
    __syncthreads();
    #pragma unroll
    for (int j = 0; j < 4; j++) {
        int i = ty + j * 8;
        dh[(size_t)(c0 + i) * C_ + r0 + tx] = __float2half(tbuf[tx][i]);
    }
}

// ---------------------------------------------------------------------------
extern "C" void kernel_launch(void* const* d_in, const int* in_sizes, int n_in,
                              void* d_out, int out_size)
{
    const float* x      = (const float*)d_in[0];
    const float* w_qkv  = (const float*)d_in[1];
    const float* w_proj = (const float*)d_in[2];
    const float* b_proj = (const float*)d_in[3];
    float* out  = (float*)d_out;
    float* attn = out + (size_t)M_ * C_;

    cudaFuncSetAttribute(qkv_gemm,      cudaFuncAttributeMaxDynamicSharedMemorySize, QK_SMEM);
    cudaFuncSetAttribute(sscore_kernel, cudaFuncAttributeMaxDynamicSharedMemorySize, SS_SMEM);
    cudaFuncSetAttribute(av_gemm,       cudaFuncAttributeMaxDynamicSharedMemorySize, AV_SMEM);
    cudaFuncSetAttribute(proj_gemm,     cudaFuncAttributeMaxDynamicSharedMemorySize, PJ_SMEM);

    // 1) input conversions (plain fp16)
    conv_x<<<M_ * C_ / 1024, 256>>>(x);
    conv_wT<0><<<dim3(QKVC / 32, C_ / 32), 256>>>(w_qkv);
    conv_wT<1><<<dim3(C_ / 32, C_ / 32), 256>>>(w_proj);

    // 2) QKV GEMM (1-term) -> q (scaled), k, vT
    qkv_gemm<<<dim3(QKVC / 128, M_ / 128), 256, QK_SMEM>>>();

    // 3) S + softmax -> attn fp32 (1-term)
    sscore_kernel<<<BH_ * 32, 256, SS_SMEM>>>(attn);

    // 4) ctx = attn(fp16) @ Vh (1-term)
    av_gemm<<<dim3(1, N_ / 128, BH_), 256, AV_SMEM>>>(attn);

    // 5) out = ctx @ w_proj + bias (1-term)
    proj_gemm<<<dim3(C_ / 128, M_ / 128), 256, PJ_SMEM>>>(out, b_proj);
}

// round 13
// speedup vs baseline: 2.5617x; 1.0944x over previous
#include <cuda_runtime.h>
#include <cuda_fp16.h>

typedef unsigned int u32;

#define B_   8
#define N_   1024
#define C_   1024
#define H_   16
#define D_   64
#define M_   (B_ * N_)     // 8192
#define QKVC 3072
#define BH_  (B_ * H_)     // 128

// ---------------- allocation-free scratch (device globals, fp16) ----------
__device__ __align__(256) __half g_xh[(size_t)M_ * C_];
__device__ __align__(256) __half g_wqh[(size_t)QKVC * C_];
__device__ __align__(256) __half g_wph[(size_t)C_ * C_];
__device__ __align__(256) __half g_qh[(size_t)BH_ * N_ * D_];
__device__ __align__(256) __half g_kh[(size_t)BH_ * N_ * D_];
__device__ __align__(256) __half g_vTh[(size_t)BH_ * D_ * N_];
__device__ __align__(256) __half g_ch[(size_t)M_ * C_];

// ---------------- helpers ----------------
__device__ __forceinline__ u32 smem_u32(const void* p) {
    u32 a;
    asm("{ .reg .u64 t; cvta.to.shared.u64 t, %1; cvt.u32.u64 %0, t; }" : "=r"(a) : "l"(p));
    return a;
}
#define CP16(dst, src) \
    asm volatile("cp.async.cg.shared.global [%0], [%1], 16;" :: "r"(dst), "l"(src) : "memory")
#define CP_COMMIT() asm volatile("cp.async.commit_group;" ::: "memory")
#define CP_WAIT(n)  asm volatile("cp.async.wait_group %0;" :: "n"(n) : "memory")

__device__ __forceinline__ void ldm4(u32& r0, u32& r1, u32& r2, u32& r3, u32 a) {
    asm volatile("ldmatrix.sync.aligned.m8n8.x4.shared.b16 {%0,%1,%2,%3}, [%4];"
        : "=r"(r0), "=r"(r1), "=r"(r2), "=r"(r3) : "r"(a));
}
__device__ __forceinline__ void mma16816(float* c, const u32* a, const u32* b) {
    asm volatile(
        "mma.sync.aligned.m16n8k16.row.col.f32.f16.f16.f32 "
        "{%0,%1,%2,%3}, {%4,%5,%6,%7}, {%8,%9}, {%0,%1,%2,%3};"
        : "+f"(c[0]), "+f"(c[1]), "+f"(c[2]), "+f"(c[3])
        : "r"(a[0]), "r"(a[1]), "r"(a[2]), "r"(a[3]), "r"(b[0]), "r"(b[1]));
}

// ---------------------------------------------------------------------------
// QKV GEMM: 1-term fp16 (xh * wh). 256 thr, 2 CTAs/SM, MA4 NA4, 3-stage ring.
// ---------------------------------------------------------------------------
#define QK_PART  10240
#define QK_STAGE (2 * QK_PART)
#define QK_SMEM  (3 * QK_STAGE)   // 61440

__global__ void __launch_bounds__(256, 2) qkv_gemm()
{
    constexpr int NC = 32;
    constexpr int MA = 4;
    constexpr int NA = 4;

    extern __shared__ char smem[];
    const u32 sb   = smem_u32(smem);
    const int tid  = threadIdx.x;
    const int wid  = tid >> 5, lane = tid & 31;
    const int g    = lane >> 2, t = lane & 3;
    const int bn   = blockIdx.x * 128;
    const int bm   = blockIdx.y * 128;
    const int wm   = (wid & 1) * 64;
    const int wn   = (wid >> 1) * 32;

    const __half *Ah = g_xh + (size_t)bm * C_;
    const __half *Bh = g_wqh + (size_t)bn * C_;

    float acc[MA][NA][4];
    #pragma unroll
    for (int i = 0; i < MA; i++)
        #pragma unroll
        for (int j = 0; j < NA; j++)
            #pragma unroll
            for (int r = 0; r < 4; r++) acc[i][j][r] = 0.0f;

    auto issue_loads = [&](int ck, int s) {
        const int kofs = ck * 32;
        const u32 base = sb + s * QK_STAGE;
        #pragma unroll
        for (int i = tid; i < 128 * 4; i += 256) {
            int r = i >> 2, sgm = i & 3;
            u32 off = (u32)(r * 80 + sgm * 16);
            const size_t go = (size_t)r * C_ + kofs + sgm * 8;
            CP16(base + off,           Ah + go);
            CP16(base + QK_PART + off, Bh + go);
        }
        CP_COMMIT();
    };

    const u32 arow = (u32)((wm + (lane & 15)) * 80 + ((lane >> 4) << 4));
    const u32 brow = (u32)((wn + (lane & 7) + ((lane >> 4) << 3)) * 80 + (((lane >> 3) & 1) << 4));

    auto do_compute = [&](int s) {
        const u32 abase = sb + s * QK_STAGE;
        const u32 bbase = abase + QK_PART;
        #pragma unroll
        for (int ks = 0; ks < 2; ks++) {
            const u32 kb = ks * 32;
            u32 a_hi[MA][4], b_hi[NA][2];
            #pragma unroll
            for (int ma = 0; ma < MA; ma++) {
                u32 ad = abase + arow + ma * 16 * 80 + kb;
                ldm4(a_hi[ma][0], a_hi[ma][1], a_hi[ma][2], a_hi[ma][3], ad);
            }
            #pragma unroll
            for (int p = 0; p < NA / 2; p++) {
                u32 bd = bbase + brow + p * 16 * 80 + kb;
                ldm4(b_hi[2*p][0], b_hi[2*p][1], b_hi[2*p+1][0], b_hi[2*p+1][1], bd);
            }
            #pragma unroll
            for (int ma = 0; ma < MA; ma++)
                #pragma unroll
                for (int na = 0; na < NA; na++)
                    mma16816(acc[ma][na], a_hi[ma], b_hi[na]);
        }
    };

    issue_loads(0, 0);
    issue_loads(1, 1);
    for (int ck = 0; ck < NC; ck++) {
        const int s = ck % 3;
        if (ck + 2 < NC) { issue_loads(ck + 2, (ck + 2) % 3); CP_WAIT(2); }
        else if (ck + 1 < NC) { CP_WAIT(1); }
        else { CP_WAIT(0); }
        __syncthreads();
        do_compute(s);
        __syncthreads();
    }

    // ---- epilogue ----
    #pragma unroll
    for (int ma = 0; ma < MA; ma++)
        #pragma unroll
        for (int na = 0; na < NA; na++)
            #pragma unroll
            for (int half = 0; half < 2; half++) {
                const int row = bm + wm + ma * 16 + g + half * 8;
                const int col = bn + wn + na * 8 + t * 2;
                float v0 = acc[ma][na][half * 2 + 0];
                float v1 = acc[ma][na][half * 2 + 1];

                const int which = col >> 10;
                const int c     = col & 1023;
                const int h     = c >> 6;
                const int d0    = c & 63;
                const int b8    = row >> 10;
                const int n     = row & 1023;
                const int bh    = b8 * H_ + h;
                if (which == 0) {
                    const size_t base = ((size_t)bh * N_ + n) * D_ + d0;
                    *(__half2*)(g_qh + base) =
                        __halves2half2(__float2half(v0 * 0.125f), __float2half(v1 * 0.125f));
                } else if (which == 1) {
                    const size_t base = ((size_t)bh * N_ + n) * D_ + d0;
                    *(__half2*)(g_kh + base) =
                        __halves2half2(__float2half(v0), __float2half(v1));
                } else {
                    const size_t vb = (size_t)bh * D_ * N_ + n;
                    g_vTh[vb + (size_t)d0 * N_]       = __float2half(v0);
                    g_vTh[vb + (size_t)(d0 + 1) * N_] = __float2half(v1);
                }
            }
}

// ---------------------------------------------------------------------------
// Fused S = qh @ kh^T -> softmax -> attn fp32 (1-term fp16). 1 CTA/SM (smem).
// ---------------------------------------------------------------------------
#define Q_OFF  0
#define K_OFF  4608
#define KSTG   18432
#define S_OFF  41472
#define S_PIT  4144
#define SS_SMEM (S_OFF + 32 * S_PIT)   // 174080

__global__ void __launch_bounds__(256, 1) sscore_kernel(float* __restrict__ attn)
{
    extern __shared__ char smem[];
    const u32 sb   = smem_u32(smem);
    const int tid  = threadIdx.x;
    const int wid  = tid >> 5, lane = tid & 31;
    const int g    = lane >> 2, t = lane & 3;

    const int bh   = blockIdx.x >> 5;
    const int row0 = (blockIdx.x & 31) * 32;
    const int wm   = (wid & 1) * 16;
    const int wn   = (wid >> 1) * 32;

    const __half* Qh = g_qh + ((size_t)bh * N_ + row0) * D_;
    const __half* Kh = g_kh + (size_t)bh * N_ * D_;

    {
        int r = tid >> 3, sgm = tid & 7;
        u32 off = (u32)(r * 144 + sgm * 16);
        *(float4*)(smem + Q_OFF + off) = *(const float4*)(Qh + r * D_ + sgm * 8);
    }

    auto issueK = [&](int c, int s) {
        const u32 base = sb + K_OFF + s * KSTG;
        const size_t ko = (size_t)c * 128 * D_;
        #pragma unroll
        for (int i = tid; i < 128 * 8; i += 256) {
            int r = i >> 3, sgm = i & 7;
            CP16(base + (u32)(r * 144 + sgm * 16), Kh + ko + r * D_ + sgm * 8);
        }
        CP_COMMIT();
    };

    const u32 arow = (u32)((wm + (lane & 15)) * 144 + ((lane >> 4) << 4));
    const u32 brow = (u32)((wn + (lane & 7) + ((lane >> 4) << 3)) * 144 + (((lane >> 3) & 1) << 4));

    issueK(0, 0);
    issueK(1, 1);
    for (int c = 0; c < 8; c++) {
        if (c < 7) CP_WAIT(1); else CP_WAIT(0);
        __syncthreads();

        const u32 kb0 = sb + K_OFF + (c & 1) * KSTG;
        float acc[4][4];
        #pragma unroll
        for (int j = 0; j < 4; j++)
            #pragma unroll
            for (int r = 0; r < 4; r++) acc[j][r] = 0.0f;

        #pragma unroll
        for (int ks = 0; ks < 4; ks++) {
            const u32 kb = ks * 32;
            u32 a_hi[4], b_hi[4][2];
            u32 ad = sb + Q_OFF + arow + kb;
            ldm4(a_hi[0], a_hi[1], a_hi[2], a_hi[3], ad);
            #pragma unroll
            for (int p = 0; p < 2; p++) {
                u32 bd = kb0 + brow + p * 16 * 144 + kb;
                ldm4(b_hi[2*p][0], b_hi[2*p][1], b_hi[2*p+1][0], b_hi[2*p+1][1], bd);
            }
            #pragma unroll
            for (int na = 0; na < 4; na++)
                mma16816(acc[na], a_hi, b_hi[na]);
        }

        #pragma unroll
        for (int na = 0; na < 4; na++)
            #pragma unroll
            for (int half = 0; half < 2; half++) {
                int row = wm + g + half * 8;
                int col = c * 128 + wn + na * 8 + t * 2;
                *(float2*)(smem + S_OFF + row * S_PIT + col * 4) =
                    make_float2(acc[na][half * 2], acc[na][half * 2 + 1]);
            }

        __syncthreads();
        if (c + 2 < 8) issueK(c + 2, c & 1);
    }

    #pragma unroll
    for (int rr = 0; rr < 4; rr++) {
        const int r = wid * 4 + rr;
        const float* Srow = (const float*)(smem + S_OFF + r * S_PIT);
        float4 f[8];
        float m = -1e30f;
        #pragma unroll
        for (int i = 0; i < 8; i++) {
            f[i] = *(const float4*)(Srow + (lane + i * 32) * 4);
            m = fmaxf(m, fmaxf(fmaxf(f[i].x, f[i].y), fmaxf(f[i].z, f[i].w)));
        }
        #pragma unroll
        for (int o = 16; o > 0; o >>= 1) m = fmaxf(m, __shfl_xor_sync(0xffffffffu, m, o));
        float s = 0.0f;
        #pragma unroll
        for (int i = 0; i < 8; i++) {
            f[i].x = __expf(f[i].x - m); f[i].y = __expf(f[i].y - m);
            f[i].z = __expf(f[i].z - m); f[i].w = __expf(f[i].w - m);
            s += f[i].x + f[i].y + f[i].z + f[i].w;
        }
        #pragma unroll
        for (int o = 16; o > 0; o >>= 1) s += __shfl_xor_sync(0xffffffffu, s, o);
        const float inv = 1.0f / s;

        float* ap = attn + ((size_t)bh * N_ + row0 + r) * N_;
        #pragma unroll
        for (int i = 0; i < 8; i++) {
            *(float4*)(ap + (lane + i * 32) * 4) =
                make_float4(f[i].x * inv, f[i].y * inv, f[i].z * inv, f[i].w * inv);
        }
    }
}

// ---------------------------------------------------------------------------
// AV GEMM: ctx = Ph @ Vh (1-term; P rounded to fp16 in smem). 2 CTAs/SM.
// ---------------------------------------------------------------------------
#define AV_ASTG   18432
#define AV_AH_OFF (3 * AV_ASTG)                    // 55296
#define AV_B_OFF  (AV_AH_OFF + 10240)              // 65536
#define AV_BSTG   5120
#define AV_SMEM   (AV_B_OFF + 3 * AV_BSTG)         // 80896

__global__ void __launch_bounds__(256, 2) av_gemm(const float* __restrict__ attn)
{
    extern __shared__ char smem[];
    const u32 sb   = smem_u32(smem);
    const int tid  = threadIdx.x;
    const int wid  = tid >> 5, lane = tid & 31;
    const int g    = lane >> 2, t = lane & 3;

    const int bm = blockIdx.y * 128;
    const int z  = blockIdx.z;
    const int b8 = z >> 4, h = z & 15;
    const int wm = (wid & 3) * 32;
    const int wn = (wid >> 2) * 32;

    const float* Ap = attn + (size_t)z * N_ * N_ + (size_t)bm * N_;
    const __half* Vh = g_vTh + (size_t)z * D_ * N_;

    float acc[2][4][4];
    #pragma unroll
    for (int i = 0; i < 2; i++)
        #pragma unroll
        for (int j = 0; j < 4; j++)
            #pragma unroll
            for (int r = 0; r < 4; r++) acc[i][j][r] = 0.0f;

    auto issue_loads = [&](int ck, int s) {
        const int kofs = ck * 32;
        const u32 abase = sb + s * AV_ASTG;
        #pragma unroll
        for (int i = tid; i < 128 * 8; i += 256) {
            int r = i >> 3, sgm = i & 7;
            CP16(abase + (u32)(r * 144 + sgm * 16), Ap + (size_t)r * N_ + kofs + sgm * 4);
        }
        const u32 bbase = sb + AV_B_OFF + s * AV_BSTG;
        #pragma unroll
        for (int i = tid; i < 64 * 4; i += 256) {
            int r = i >> 2, sgm = i & 3;
            CP16(bbase + (u32)(r * 80 + sgm * 16), Vh + (size_t)r * N_ + kofs + sgm * 8);
        }
        CP_COMMIT();
    };

    const u32 arow = (u32)((wm + (lane & 15)) * 80 + ((lane >> 4) << 4));
    const u32 brow = (u32)((wn + (lane & 7) + ((lane >> 4) << 3)) * 80 + (((lane >> 3) & 1) << 4));

    issue_loads(0, 0);
    issue_loads(1, 1);
    issue_loads(2, 2);
    for (int ck = 0; ck < 32; ck++) {
        const int s = ck % 3;
        if (ck <= 29) CP_WAIT(2);
        else if (ck == 30) CP_WAIT(1);
        else CP_WAIT(0);
        __syncthreads();

        {
            const char* src = smem + s * AV_ASTG + (tid >> 1) * 144 + (tid & 1) * 64;
            float4 v0 = *(const float4*)(src);
            float4 v1 = *(const float4*)(src + 16);
            float4 v2 = *(const float4*)(src + 32);
            float4 v3 = *(const float4*)(src + 48);
            __half2 p0 = __halves2half2(__float2half(v0.x), __float2half(v0.y));
            __half2 p1 = __halves2half2(__float2half(v0.z), __float2half(v0.w));
            __half2 p2 = __halves2half2(__float2half(v1.x), __float2half(v1.y));
            __half2 p3 = __halves2half2(__float2half(v1.z), __float2half(v1.w));
            __half2 p4 = __halves2half2(__float2half(v2.x), __float2half(v2.y));
            __half2 p5 = __halves2half2(__float2half(v2.z), __float2half(v2.w));
            __half2 p6 = __halves2half2(__float2half(v3.x), __float2half(v3.y));
            __half2 p7 = __halves2half2(__float2half(v3.z), __float2half(v3.w));
            char* dh = smem + AV_AH_OFF + (tid >> 1) * 80 + (tid & 1) * 32;
            *(uint4*)dh        = make_uint4(*(u32*)&p0, *(u32*)&p1, *(u32*)&p2, *(u32*)&p3);
            *(uint4*)(dh + 16) = make_uint4(*(u32*)&p4, *(u32*)&p5, *(u32*)&p6, *(u32*)&p7);
        }
        __syncthreads();

        {
            const u32 ah0 = sb + AV_AH_OFF;
            const u32 bb0 = sb + AV_B_OFF + s * AV_BSTG;
            #pragma unroll
            for (int ks = 0; ks < 2; ks++) {
                const u32 kb = ks * 32;
                u32 a_hi[2][4], b_hi[4][2];
                #pragma unroll
                for (int ma = 0; ma < 2; ma++) {
                    u32 ad = ah0 + arow + ma * 16 * 80 + kb;
                    ldm4(a_hi[ma][0], a_hi[ma][1], a_hi[ma][2], a_hi[ma][3], ad);
                }
                #pragma unroll
                for (int p = 0; p < 2; p++) {
                    u32 bd = bb0 + brow + p * 16 * 80 + kb;
                    ldm4(b_hi[2*p][0], b_hi[2*p][1], b_hi[2*p+1][0], b_hi[2*p+1][1], bd);
                }
                #pragma unroll
                for (int ma = 0; ma < 2; ma++)
                    #pragma unroll
                    for (int na = 0; na < 4; na++)
                        mma16816(acc[ma][na], a_hi[ma], b_hi[na]);
            }
        }
        __syncthreads();
        if (ck + 3 < 32) issue_loads(ck + 3, s);
    }

    #pragma unroll
    for (int ma = 0; ma < 2; ma++)
        #pragma unroll
        for (int na = 0; na < 4; na++)
            #pragma unroll
            for (int half = 0; half < 2; half++) {
                const int row = bm + wm + ma * 16 + g + half * 8;
                const int col = wn + na * 8 + t * 2;
                const size_t base = ((size_t)(b8 * N_ + row)) * C_ + h * 64 + col;
                *(__half2*)(g_ch + base) =
                    __halves2half2(__float2half(acc[ma][na][half * 2 + 0]),
                                   __float2half(acc[ma][na][half * 2 + 1]));
            }
}

// ---------------------------------------------------------------------------
// Projection GEMM: out = ch @ wph + bias (1-term). 2 CTAs/SM.
// ---------------------------------------------------------------------------
#define PJ_PART  10240
#define PJ_STAGE (2 * PJ_PART)
#define PJ_SMEM  (3 * PJ_STAGE)   // 61440

__global__ void __launch_bounds__(256, 2) proj_gemm(float* __restrict__ out,
                                                    const float* __restrict__ bias)
{
    constexpr int NC = 32;
    constexpr int MA = 4;
    constexpr int NA = 4;

    extern __shared__ char smem[];
    const u32 sb   = smem_u32(smem);
    const int tid  = threadIdx.x;
    const int wid  = tid >> 5, lane = tid & 31;
    const int g    = lane >> 2, t = lane & 3;
    const int bn   = blockIdx.x * 128;
    const int bm   = blockIdx.y * 128;
    const int wm   = (wid & 1) * 64;
    const int wn   = (wid >> 1) * 32;

    const __half *Ah = g_ch + (size_t)bm * C_;
    const __half *Bh = g_wph + (size_t)bn * C_;

    float acc[MA][NA][4];
    #pragma unroll
    for (int i = 0; i < MA; i++)
        #pragma unroll
        for (int j = 0; j < NA; j++)
            #pragma unroll
            for (int r = 0; r < 4; r++) acc[i][j][r] = 0.0f;

    auto issue_loads = [&](int ck, int s) {
        const int kofs = ck * 32;
        const u32 base = sb + s * PJ_STAGE;
        #pragma unroll
        for (int i = tid; i < 128 * 4; i += 256) {
            int r = i >> 2, sgm = i & 3;
            u32 off = (u32)(r * 80 + sgm * 16);
            const size_t go = (size_t)r * C_ + kofs + sgm * 8;
            CP16(base + off,           Ah + go);
            CP16(base + PJ_PART + off, Bh + go);
        }
        CP_COMMIT();
    };

    const u32 arow = (u32)((wm + (lane & 15)) * 80 + ((lane >> 4) << 4));
    const u32 brow = (u32)((wn + (lane & 7) + ((lane >> 4) << 3)) * 80 + (((lane >> 3) & 1) << 4));

    auto do_compute = [&](int s) {
        const u32 abase = sb + s * PJ_STAGE;
        const u32 bbase = abase + PJ_PART;
        #pragma unroll
        for (int ks = 0; ks < 2; ks++) {
            const u32 kb = ks * 32;
            u32 a_hi[MA][4], b_hi[NA][2];
            #pragma unroll
            for (int ma = 0; ma < MA; ma++) {
                u32 ad = abase + arow + ma * 16 * 80 + kb;
                ldm4(a_hi[ma][0], a_hi[ma][1], a_hi[ma][2], a_hi[ma][3], ad);
            }
            #pragma unroll
            for (int p = 0; p < NA / 2; p++) {
                u32 bd = bbase + brow + p * 16 * 80 + kb;
                ldm4(b_hi[2*p][0], b_hi[2*p][1], b_hi[2*p+1][0], b_hi[2*p+1][1], bd);
            }
            #pragma unroll
            for (int ma = 0; ma < MA; ma++)
                #pragma unroll
                for (int na = 0; na < NA; na++)
                    mma16816(acc[ma][na], a_hi[ma], b_hi[na]);
        }
    };

    issue_loads(0, 0);
    issue_loads(1, 1);
    for (int ck = 0; ck < NC; ck++) {
        const int s = ck % 3;
        if (ck + 2 < NC) { issue_loads(ck + 2, (ck + 2) % 3); CP_WAIT(2); }
        else if (ck + 1 < NC) { CP_WAIT(1); }
        else { CP_WAIT(0); }
        __syncthreads();
        do_compute(s);
        __syncthreads();
    }

    #pragma unroll
    for (int ma = 0; ma < MA; ma++)
        #pragma unroll
        for (int na = 0; na < NA; na++)
            #pragma unroll
            for (int half = 0; half < 2; half++) {
                const int row = bm + wm + ma * 16 + g + half * 8;
                const int col = bn + wn + na * 8 + t * 2;
                float* dst = out + (size_t)row * C_ + col;
                *(float2*)dst = make_float2(acc[ma][na][half * 2 + 0] + bias[col],
                                            acc[ma][na][half * 2 + 1] + bias[col + 1]);
            }
}

// ---------------- conversion kernels ----------------
__global__ void __launch_bounds__(256) conv_x(const float* __restrict__ s)
{
    int i = blockIdx.x * 256 + threadIdx.x;
    float4 v = ((const float4*)s)[i];
    __half2* hp = (__half2*)g_xh;
    hp[i * 2]     = __halves2half2(__float2half(v.x), __float2half(v.y));
    hp[i * 2 + 1] = __halves2half2(__float2half(v.z), __float2half(v.w));
}

template <int W>
__global__ void __launch_bounds__(256) conv_wT(const float* __restrict__ s)
{
    constexpr int Cc = (W == 0) ? QKVC : C_;
    __half* dh = (W == 0) ? g_wqh : g_wph;

    __shared__ float tbuf[32][33];
    const int tx = threadIdx.x & 31, ty = threadIdx.x >> 5;
    const int c0 = blockIdx.x * 32, r0 = blockIdx.y * 32;
    #pragma unroll
    for (int j = 0; j < 4; j++)
        tbuf[ty + j * 8][tx] = s[(size_t)(r0 + ty + j * 8) * Cc + c0 + tx];
    __syncthreads();
    #pragma unroll
    for (int j = 0; j < 4; j++) {
        int i = ty + j * 8;
        dh[(size_t)(c0 + i) * C_ + r0 + tx] = __float2half(tbuf[tx][i]);
    }
}

// ---------------------------------------------------------------------------
extern "C" void kernel_launch(void* const* d_in, const int* in_sizes, int n_in,
                              void* d_out, int out_size)
{
    const float* x      = (const float*)d_in[0];
    const float* w_qkv  = (const float*)d_in[1];
    const float* w_proj = (const float*)d_in[2];
    const float* b_proj = (const float*)d_in[3];
    float* out  = (float*)d_out;
    float* attn = out + (size_t)M_ * C_;

    cudaFuncSetAttribute(qkv_gemm,      cudaFuncAttributeMaxDynamicSharedMemorySize, QK_SMEM);
    cudaFuncSetAttribute(sscore_kernel, cudaFuncAttributeMaxDynamicSharedMemorySize, SS_SMEM);
    cudaFuncSetAttribute(av_gemm,       cudaFuncAttributeMaxDynamicSharedMemorySize, AV_SMEM);
    cudaFuncSetAttribute(proj_gemm,     cudaFuncAttributeMaxDynamicSharedMemorySize, PJ_SMEM);

    // 1) input conversions (plain fp16)
    conv_x<<<M_ * C_ / 1024, 256>>>(x);
    conv_wT<0><<<dim3(QKVC / 32, C_ / 32), 256>>>(w_qkv);
    conv_wT<1><<<dim3(C_ / 32, C_ / 32), 256>>>(w_proj);

    // 2) QKV GEMM (1-term) -> q (scaled), k, vT
    qkv_gemm<<<dim3(QKVC / 128, M_ / 128), 256, QK_SMEM>>>();

    // 3) S + softmax -> attn fp32 (1-term)
    sscore_kernel<<<BH_ * 32, 256, SS_SMEM>>>(attn);

    // 4) ctx = attn(fp16) @ Vh (1-term)
    av_gemm<<<dim3(1, N_ / 128, BH_), 256, AV_SMEM>>>(attn);

    // 5) out = ctx @ w_proj + bias (1-term)
    proj_gemm<<<dim3(C_ / 128, M_ / 128), 256, PJ_SMEM>>>(out, b_proj);
}